// round 8
// baseline (speedup 1.0000x reference)
#include <cuda_runtime.h>
#include <cuda_bf16.h>
#include <cstdint>

#define N_NODES 50000
#define N_EDGES 800000
#define N_GRAPHS 1024

// ---------------- device-global scratch (allocation-free rule) -------------
__device__ float g_h1[(size_t)N_NODES * 256];   // also reused for FC z output
__device__ float g_h2[(size_t)N_NODES * 512];
__device__ __nv_bfloat16 g_agg_hi[(size_t)N_NODES * 512];
__device__ __nv_bfloat16 g_agg_lo[(size_t)N_NODES * 512];
__device__ __nv_bfloat16 g_bufA_hi[(size_t)N_NODES * 512];
__device__ __nv_bfloat16 g_bufA_lo[(size_t)N_NODES * 512];
__device__ __nv_bfloat16 g_bufB_hi[(size_t)N_NODES * 512];
__device__ __nv_bfloat16 g_bufB_lo[(size_t)N_NODES * 512];
// transposed weights bf16 hi/lo [M][Kpad]
// W1r:0(256x96) W1o:24576 W2r:49152(512x256) W2o:180224
// W3r:311296(512x512) W3o:573440 Wfc:835584(128x512)  total 901120
__device__ __nv_bfloat16 g_wt_hi[901120];
__device__ __nv_bfloat16 g_wt_lo[901120];
// CSR
__device__ int g_cnt[N_NODES];
__device__ int g_off[N_NODES + 1];
__device__ int g_cur[N_NODES];
__device__ int g_srcs[N_EDGES];
__device__ int g_bsum[64];

// ---------------------------------------------------------------------------
__global__ void zero_kernel(float4* __restrict__ p, int n4) {
    int i = blockIdx.x * blockDim.x + threadIdx.x;
    int stride = gridDim.x * blockDim.x;
    float4 z = make_float4(0.f, 0.f, 0.f, 0.f);
    for (; i < n4; i += stride) p[i] = z;
}

__global__ void zero_int(int* __restrict__ p, int n) {
    int i = blockIdx.x * blockDim.x + threadIdx.x;
    if (i < n) p[i] = 0;
}

// ---------------------------------------------------------------------------
// Fused weight prep: all 7 weights, W [K,M] fp32 -> hi/lo [M,Kpad] transposed
// ---------------------------------------------------------------------------
struct PrepArgs {
    const float* W[7];
    int K[7];
    int M[7];
    int Kpad[7];
    int off[7];
};

__global__ void prep_all(PrepArgs a,
                         __nv_bfloat16* __restrict__ hi,
                         __nv_bfloat16* __restrict__ lo) {
    int seg = blockIdx.y;
    int idx = blockIdx.x * blockDim.x + threadIdx.x;
    int Kpad = a.Kpad[seg];
    if (idx >= a.M[seg] * Kpad) return;
    int n = idx / Kpad, k = idx % Kpad;
    int K = a.K[seg];
    float v = (k < K) ? a.W[seg][(size_t)k * a.M[seg] + n] : 0.f;
    __nv_bfloat16 h = __float2bfloat16(v);
    size_t o = (size_t)a.off[seg] + idx;
    hi[o] = h;
    lo[o] = __float2bfloat16(v - __bfloat162float(h));
}

// x [N,78] fp32 -> hi/lo [N,96] bf16 padded
__global__ void prep_x(const float* __restrict__ x,
                       __nv_bfloat16* __restrict__ hi,
                       __nv_bfloat16* __restrict__ lo) {
    int idx = blockIdx.x * blockDim.x + threadIdx.x;
    if (idx >= N_NODES * 96) return;
    int n = idx / 96, k = idx % 96;
    float v = (k < 78) ? x[(size_t)n * 78 + k] : 0.f;
    __nv_bfloat16 h = __float2bfloat16(v);
    hi[idx] = h;
    lo[idx] = __float2bfloat16(v - __bfloat162float(h));
}

// ---------------------------------------------------------------------------
// CSR build
// ---------------------------------------------------------------------------
__global__ void hist_kernel(const int* __restrict__ ei) {
    int e = blockIdx.x * blockDim.x + threadIdx.x;
    if (e < N_EDGES) atomicAdd(&g_cnt[ei[N_EDGES + e]], 1);
}

__global__ void scan1(void) {
    __shared__ int sm[1024];
    int tid = threadIdx.x;
    int i = blockIdx.x * 1024 + tid;
    int v = (i < N_NODES) ? g_cnt[i] : 0;
    sm[tid] = v;
    __syncthreads();
    for (int o = 1; o < 1024; o <<= 1) {
        int t = (tid >= o) ? sm[tid - o] : 0;
        __syncthreads();
        sm[tid] += t;
        __syncthreads();
    }
    if (i < N_NODES) g_off[i] = sm[tid] - v;
    if (tid == 1023) g_bsum[blockIdx.x] = sm[1023];
}

__global__ void scan2(int nblk) {
    if (threadIdx.x == 0) {
        int run = 0;
        for (int b = 0; b < nblk; ++b) {
            int t = g_bsum[b];
            g_bsum[b] = run;
            run += t;
        }
    }
}

__global__ void scan3(void) {
    int i = blockIdx.x * blockDim.x + threadIdx.x;
    if (i < N_NODES) {
        int o = g_off[i] + g_bsum[i >> 10];
        g_off[i] = o;
        g_cur[i] = o;
    }
    if (i == 0) g_off[N_NODES] = N_EDGES;
}

__global__ void fill_kernel(const int* __restrict__ ei) {
    int e = blockIdx.x * blockDim.x + threadIdx.x;
    if (e >= N_EDGES) return;
    int s = ei[e], t = ei[N_EDGES + e];
    int pos = atomicAdd(&g_cur[t], 1);
    g_srcs[pos] = s;
}

// ---------------------------------------------------------------------------
// CSR gather -> bf16 hi/lo.  Warp per node.
// ---------------------------------------------------------------------------
__global__ void gather78(const float* __restrict__ x,
                         __nv_bfloat16* __restrict__ ahi,
                         __nv_bfloat16* __restrict__ alo) {
    int n = (blockIdx.x * blockDim.x + threadIdx.x) >> 5;
    int lane = threadIdx.x & 31;
    if (n >= N_NODES) return;
    int jb = g_off[n], je = g_off[n + 1];
    float a0 = 0.f, a1 = 0.f, a2 = 0.f;
    for (int j = jb; j < je; ++j) {
        const float* xr = x + (size_t)g_srcs[j] * 78;
        a0 += __ldg(xr + lane);
        a1 += __ldg(xr + lane + 32);
        if (lane < 14) a2 += __ldg(xr + lane + 64);
    }
    size_t base = (size_t)n * 96;
    float vals[3] = {a0, a1, (lane < 14) ? a2 : 0.f};
    #pragma unroll
    for (int i = 0; i < 3; ++i) {
        __nv_bfloat16 h = __float2bfloat16(vals[i]);
        ahi[base + lane + i * 32] = h;
        alo[base + lane + i * 32] = __float2bfloat16(vals[i] - __bfloat162float(h));
    }
}

__global__ void gather_vec4(const float* __restrict__ x, int d,
                            __nv_bfloat16* __restrict__ ahi,
                            __nv_bfloat16* __restrict__ alo) {
    int n = (blockIdx.x * blockDim.x + threadIdx.x) >> 5;
    int lane = threadIdx.x & 31;
    if (n >= N_NODES) return;
    int jb = g_off[n], je = g_off[n + 1];
    int ni = d >> 7;
    float4 acc[4];
    #pragma unroll
    for (int i = 0; i < 4; ++i) acc[i] = make_float4(0.f, 0.f, 0.f, 0.f);
    for (int j = jb; j < je; ++j) {
        const float4* xr = (const float4*)(x + (size_t)g_srcs[j] * d);
        #pragma unroll 4
        for (int i = 0; i < ni; ++i) {
            float4 v = __ldg(xr + lane + i * 32);
            acc[i].x += v.x; acc[i].y += v.y; acc[i].z += v.z; acc[i].w += v.w;
        }
    }
    for (int i = 0; i < ni; ++i) {
        int c = (lane + i * 32) * 4;
        float4 a = acc[i];
        __nv_bfloat162 h01 = __floats2bfloat162_rn(a.x, a.y);
        __nv_bfloat162 h23 = __floats2bfloat162_rn(a.z, a.w);
        __nv_bfloat162 l01 = __floats2bfloat162_rn(a.x - __bfloat162float(h01.x),
                                                   a.y - __bfloat162float(h01.y));
        __nv_bfloat162 l23 = __floats2bfloat162_rn(a.z - __bfloat162float(h23.x),
                                                   a.w - __bfloat162float(h23.y));
        *(uint2*)(ahi + (size_t)n * d + c) =
            make_uint2(*(unsigned*)&h01, *(unsigned*)&h23);
        *(uint2*)(alo + (size_t)n * d + c) =
            make_uint2(*(unsigned*)&l01, *(unsigned*)&l23);
    }
}

// ---------------------------------------------------------------------------
// mma / ldmatrix / cp.async helpers
// ---------------------------------------------------------------------------
__device__ __forceinline__ void mma_bf16(float* c, const unsigned* a,
                                         unsigned b0, unsigned b1) {
    asm volatile(
        "mma.sync.aligned.m16n8k16.row.col.f32.bf16.bf16.f32 "
        "{%0,%1,%2,%3}, {%4,%5,%6,%7}, {%8,%9}, {%0,%1,%2,%3};"
        : "+f"(c[0]), "+f"(c[1]), "+f"(c[2]), "+f"(c[3])
        : "r"(a[0]), "r"(a[1]), "r"(a[2]), "r"(a[3]), "r"(b0), "r"(b1));
}

__device__ __forceinline__ void ldm_x4(unsigned* r, uint32_t addr) {
    asm volatile(
        "ldmatrix.sync.aligned.m8n8.x4.shared.b16 {%0,%1,%2,%3}, [%4];"
        : "=r"(r[0]), "=r"(r[1]), "=r"(r[2]), "=r"(r[3]) : "r"(addr));
}

__device__ __forceinline__ void cpa16(uint32_t d, const void* s, int sz) {
    asm volatile("cp.async.cg.shared.global [%0], [%1], 16, %2;"
                 :: "r"(d), "l"(s), "r"(sz) : "memory");
}

// ---------------------------------------------------------------------------
// Dual/single GEMM (bf16 hi/lo 3-term split), cp.async double-buffered.
//   C = act(A1 @ B1 [+ A2 @ B2] + bias),  act = ReLU if do_relu
// Operands bf16 hi/lo [rows][Kpad], K contiguous.  Tiles 128x128, chunk K=32.
// Dynamic smem: 2 stages x (Ah,Al,Bh,Bl) x 128x40 bf16 = 81920 B.
// B fragments loaded pairwise via ldmatrix.x4 (2 nt tiles / instruction).
// ---------------------------------------------------------------------------
#define RS 40
#define TILE_B 10240
#define STAGE_B 40960

__global__ __launch_bounds__(256, 2)
void dual_gemm_bf16(const __nv_bfloat16* __restrict__ A1h,
                    const __nv_bfloat16* __restrict__ A1l,
                    const __nv_bfloat16* __restrict__ A2h,
                    const __nv_bfloat16* __restrict__ A2l,
                    const __nv_bfloat16* __restrict__ B1h,
                    const __nv_bfloat16* __restrict__ B1l,
                    const __nv_bfloat16* __restrict__ B2h,
                    const __nv_bfloat16* __restrict__ B2l,
                    const float* __restrict__ bias, float* __restrict__ C,
                    __nv_bfloat16* __restrict__ Chi,
                    __nv_bfloat16* __restrict__ Clo,
                    int N, int Kpad, int M, int do_relu) {
    extern __shared__ __align__(16) char dynsmem[];
    uint32_t ubase = (uint32_t)__cvta_generic_to_shared(dynsmem);

    int tid = threadIdx.x;
    int lane = tid & 31, wid = tid >> 5;
    int wr = wid & 3, wc = wid >> 2;
    int m0w = wr * 32, n0w = wc * 64;
    int gid = lane >> 2, tig = lane & 3;

    int rowBase = blockIdx.y * 128;
    int colBase = blockIdx.x * 128;

    // A x4 lane addressing: rows 0..15 across two 8-row groups, 16B k-chunks
    int a_row = (lane & 7) + ((lane >> 3) & 1) * 8;
    int a_koff = (lane >> 4) * 16;
    // B x4 pairwise: rows 0..15 (two nt tiles), k chunks 0/16B
    int b4_row = (lane & 7) + ((lane >> 4) << 3);
    int b4_koff = ((lane >> 3) & 1) * 16;

    int lr0 = tid >> 2, lc0 = tid & 3;
    int lr1 = (tid + 256) >> 2, lc1 = tid & 3;

    float acc[2][8][4];
    #pragma unroll
    for (int mt = 0; mt < 2; mt++)
        #pragma unroll
        for (int nt = 0; nt < 8; nt++)
            #pragma unroll
            for (int i = 0; i < 4; i++) acc[mt][nt][i] = 0.f;

    const int nch = Kpad >> 5;
    const int npass = (A2h != nullptr) ? 2 : 1;
    const int T = npass * nch;

    auto load_iter = [&](int it, int stage) {
        int pass = (it >= nch) ? 1 : 0;
        int ch = it - pass * nch;
        int k0 = ch << 5;
        const __nv_bfloat16* AH = pass ? A2h : A1h;
        const __nv_bfloat16* AL = pass ? A2l : A1l;
        const __nv_bfloat16* BH = pass ? B2h : B1h;
        const __nv_bfloat16* BL = pass ? B2l : B1l;
        uint32_t sb = ubase + stage * STAGE_B;
        {
            int gr0 = rowBase + lr0;
            int gr1 = rowBase + lr1;
            int g0 = (gr0 < N) ? gr0 : 0, s0 = (gr0 < N) ? 16 : 0;
            int g1 = (gr1 < N) ? gr1 : 0, s1 = (gr1 < N) ? 16 : 0;
            size_t o0 = (size_t)g0 * Kpad + k0 + lc0 * 8;
            size_t o1 = (size_t)g1 * Kpad + k0 + lc1 * 8;
            cpa16(sb + lr0 * 80 + lc0 * 16, AH + o0, s0);
            cpa16(sb + lr1 * 80 + lc1 * 16, AH + o1, s1);
            cpa16(sb + TILE_B + lr0 * 80 + lc0 * 16, AL + o0, s0);
            cpa16(sb + TILE_B + lr1 * 80 + lc1 * 16, AL + o1, s1);
        }
        {
            size_t o0 = (size_t)(colBase + lr0) * Kpad + k0 + lc0 * 8;
            size_t o1 = (size_t)(colBase + lr1) * Kpad + k0 + lc1 * 8;
            cpa16(sb + 2 * TILE_B + lr0 * 80 + lc0 * 16, BH + o0, 16);
            cpa16(sb + 2 * TILE_B + lr1 * 80 + lc1 * 16, BH + o1, 16);
            cpa16(sb + 3 * TILE_B + lr0 * 80 + lc0 * 16, BL + o0, 16);
            cpa16(sb + 3 * TILE_B + lr1 * 80 + lc1 * 16, BL + o1, 16);
        }
        asm volatile("cp.async.commit_group;" ::: "memory");
    };

    load_iter(0, 0);

    #pragma unroll 1
    for (int it = 0; it < T; ++it) {
        if (it + 1 < T) {
            load_iter(it + 1, (it + 1) & 1);
            asm volatile("cp.async.wait_group 1;" ::: "memory");
        } else {
            asm volatile("cp.async.wait_group 0;" ::: "memory");
        }
        __syncthreads();

        uint32_t sb = ubase + (it & 1) * STAGE_B;
        uint32_t uAh = sb, uAl = sb + TILE_B;
        uint32_t uBh = sb + 2 * TILE_B, uBl = sb + 3 * TILE_B;

        #pragma unroll
        for (int ks = 0; ks < 2; ++ks) {
            int kb = ks * 32;
            unsigned ah[2][4], al[2][4];
            #pragma unroll
            for (int mt = 0; mt < 2; mt++) {
                uint32_t ao = (uint32_t)((m0w + mt * 16 + a_row) * 80
                                         + kb + a_koff);
                ldm_x4(ah[mt], uAh + ao);
                ldm_x4(al[mt], uAl + ao);
            }
            #pragma unroll
            for (int ntp = 0; ntp < 4; ntp++) {
                uint32_t bo = (uint32_t)((n0w + ntp * 16 + b4_row) * 80
                                         + kb + b4_koff);
                unsigned bh[4], bl[4];
                ldm_x4(bh, uBh + bo);
                ldm_x4(bl, uBl + bo);
                #pragma unroll
                for (int sub = 0; sub < 2; sub++) {
                    int nt = ntp * 2 + sub;
                    #pragma unroll
                    for (int mt = 0; mt < 2; mt++) {
                        mma_bf16(acc[mt][nt], ah[mt], bh[2 * sub], bh[2 * sub + 1]);
                        mma_bf16(acc[mt][nt], al[mt], bh[2 * sub], bh[2 * sub + 1]);
                        mma_bf16(acc[mt][nt], ah[mt], bl[2 * sub], bl[2 * sub + 1]);
                    }
                }
            }
        }
        __syncthreads();
    }

    // ---- Epilogue ----
    #pragma unroll
    for (int mt = 0; mt < 2; mt++) {
        #pragma unroll
        for (int nt = 0; nt < 8; nt++) {
            int r = rowBase + m0w + mt * 16 + gid;
            int c = colBase + n0w + nt * 8 + tig * 2;
            float b0v = bias[c], b1v = bias[c + 1];
            #pragma unroll
            for (int half = 0; half < 2; ++half) {
                int rr = r + half * 8;
                if (rr >= N) continue;
                float v0 = acc[mt][nt][2 * half + 0] + b0v;
                float v1 = acc[mt][nt][2 * half + 1] + b1v;
                if (do_relu) {
                    v0 = v0 > 0.f ? v0 : 0.f;
                    v1 = v1 > 0.f ? v1 : 0.f;
                }
                size_t o = (size_t)rr * M + c;
                if (C) {
                    C[o] = v0;
                    C[o + 1] = v1;
                }
                if (Chi) {
                    __nv_bfloat162 hh = __floats2bfloat162_rn(v0, v1);
                    __nv_bfloat162 ll = __floats2bfloat162_rn(
                        v0 - __bfloat162float(hh.x), v1 - __bfloat162float(hh.y));
                    *(unsigned*)(Chi + o) = *(unsigned*)&hh;
                    *(unsigned*)(Clo + o) = *(unsigned*)&ll;
                }
            }
        }
    }
}

// ---------------------------------------------------------------------------
// LayerNorm(128) + ReLU + graph pooling over precomputed z = fc(h3).
// ---------------------------------------------------------------------------
#define LN_ROWS 16

__global__ __launch_bounds__(128)
void ln_pool(const float* __restrict__ z, const float* __restrict__ lng,
             const float* __restrict__ lnb, const int* __restrict__ batch,
             float* __restrict__ xa, float* __restrict__ pooled, int N) {
    __shared__ float ws[4], ws2[4];
    int c = threadIdx.x;
    int lane = c & 31;
    int wid = c >> 5;
    int r0 = blockIdx.x * LN_ROWS;
    int nr = min(LN_ROWS, N - r0);

    float g = lng[c], b = lnb[c];
    float pacc = 0.f;
    int curg = -1;
    for (int r = 0; r < nr; ++r) {
        float v = z[(size_t)(r0 + r) * 128 + c];
        float s = v, s2 = v * v;
        #pragma unroll
        for (int o = 16; o > 0; o >>= 1) {
            s  += __shfl_xor_sync(0xffffffffu, s, o);
            s2 += __shfl_xor_sync(0xffffffffu, s2, o);
        }
        __syncthreads();
        if (lane == 0) { ws[wid] = s; ws2[wid] = s2; }
        __syncthreads();
        float sum = ws[0] + ws[1] + ws[2] + ws[3];
        float sum2 = ws2[0] + ws2[1] + ws2[2] + ws2[3];
        float mu = sum * (1.f / 128.f);
        float var = sum2 * (1.f / 128.f) - mu * mu;
        float zz = (v - mu) * rsqrtf(var + 1e-5f) * g + b;
        float relu = zz > 0.f ? zz : 0.f;
        xa[(size_t)(r0 + r) * 128 + c] = relu;

        int gb = batch[r0 + r];
        if (gb != curg) {
            if (curg >= 0) atomicAdd(&pooled[(size_t)curg * 128 + c], pacc);
            curg = gb;
            pacc = 0.f;
        }
        pacc += relu;
    }
    if (curg >= 0) atomicAdd(&pooled[(size_t)curg * 128 + c], pacc);
}

// ---------------------------------------------------------------------------
// Launch
// ---------------------------------------------------------------------------
extern "C" void kernel_launch(void* const* d_in, const int* in_sizes, int n_in,
                              void* d_out, int out_size) {
    const float* x     = (const float*)d_in[0];
    const int*   ei    = (const int*)d_in[1];
    const int*   batch = (const int*)d_in[2];
    const float* W1r = (const float*)d_in[3];
    const float* b1  = (const float*)d_in[4];
    const float* W1o = (const float*)d_in[5];
    const float* W2r = (const float*)d_in[6];
    const float* b2  = (const float*)d_in[7];
    const float* W2o = (const float*)d_in[8];
    const float* W3r = (const float*)d_in[9];
    const float* b3  = (const float*)d_in[10];
    const float* W3o = (const float*)d_in[11];
    const float* Wfc = (const float*)d_in[12];
    const float* bfc = (const float*)d_in[13];
    const float* lng = (const float*)d_in[14];
    const float* lnb = (const float*)d_in[15];

    float* out = (float*)d_out;
    float* x_atom = out;
    float* pooled = out + (size_t)N_NODES * 128;

    float *h1, *h2;
    __nv_bfloat16 *aggh, *aggl, *bAh, *bAl, *bBh, *bBl, *wth, *wtl;
    cudaGetSymbolAddress((void**)&h1, g_h1);
    cudaGetSymbolAddress((void**)&h2, g_h2);
    cudaGetSymbolAddress((void**)&aggh, g_agg_hi);
    cudaGetSymbolAddress((void**)&aggl, g_agg_lo);
    cudaGetSymbolAddress((void**)&bAh, g_bufA_hi);
    cudaGetSymbolAddress((void**)&bAl, g_bufA_lo);
    cudaGetSymbolAddress((void**)&bBh, g_bufB_hi);
    cudaGetSymbolAddress((void**)&bBl, g_bufB_lo);
    cudaGetSymbolAddress((void**)&wth, g_wt_hi);
    cudaGetSymbolAddress((void**)&wtl, g_wt_lo);

    cudaFuncSetAttribute(dual_gemm_bf16,
                         cudaFuncAttributeMaxDynamicSharedMemorySize, 81920);

    const int gridY = (N_NODES + 127) / 128;
    const int gatherBlocks = (N_NODES * 32 + 255) / 256;

    // ---- Weight prep (single fused launch) ----
    {
        PrepArgs pa;
        pa.W[0] = W1r; pa.K[0] = 78;  pa.M[0] = 256; pa.Kpad[0] = 96;  pa.off[0] = 0;
        pa.W[1] = W1o; pa.K[1] = 78;  pa.M[1] = 256; pa.Kpad[1] = 96;  pa.off[1] = 24576;
        pa.W[2] = W2r; pa.K[2] = 256; pa.M[2] = 512; pa.Kpad[2] = 256; pa.off[2] = 49152;
        pa.W[3] = W2o; pa.K[3] = 256; pa.M[3] = 512; pa.Kpad[3] = 256; pa.off[3] = 180224;
        pa.W[4] = W3r; pa.K[4] = 512; pa.M[4] = 512; pa.Kpad[4] = 512; pa.off[4] = 311296;
        pa.W[5] = W3o; pa.K[5] = 512; pa.M[5] = 512; pa.Kpad[5] = 512; pa.off[5] = 573440;
        pa.W[6] = Wfc; pa.K[6] = 512; pa.M[6] = 128; pa.Kpad[6] = 512; pa.off[6] = 835584;
        dim3 grid((512 * 512 + 255) / 256, 7);
        prep_all<<<grid, 256>>>(pa, wth, wtl);
    }
    prep_x<<<(N_NODES * 96 + 255) / 256, 256>>>(x, bAh, bAl);

    // ---- CSR build ----
    {
        int* pcnt; cudaGetSymbolAddress((void**)&pcnt, g_cnt);
        zero_int<<<(N_NODES + 255) / 256, 256>>>(pcnt, N_NODES);
    }
    hist_kernel<<<(N_EDGES + 255) / 256, 256>>>(ei);
    scan1<<<(N_NODES + 1023) / 1024, 1024>>>();
    scan2<<<1, 32>>>((N_NODES + 1023) / 1024);
    scan3<<<(N_NODES + 255) / 256, 256>>>();
    fill_kernel<<<(N_EDGES + 255) / 256, 256>>>(ei);

    // ---- Layer 1: 78 -> 256 ----
    gather78<<<gatherBlocks, 256>>>(x, aggh, aggl);
    {
        dim3 grid(2, gridY);
        dual_gemm_bf16<<<grid, 256, 81920>>>(aggh, aggl, bAh, bAl,
                                             wth + 0, wtl + 0,
                                             wth + 24576, wtl + 24576,
                                             b1, h1, bBh, bBl,
                                             N_NODES, 96, 256, 1);
    }

    // ---- Layer 2: 256 -> 512 ----
    gather_vec4<<<gatherBlocks, 256>>>(h1, 256, aggh, aggl);
    {
        dim3 grid(4, gridY);
        dual_gemm_bf16<<<grid, 256, 81920>>>(aggh, aggl, bBh, bBl,
                                             wth + 49152, wtl + 49152,
                                             wth + 180224, wtl + 180224,
                                             b2, h2, bAh, bAl,
                                             N_NODES, 256, 512, 1);
    }

    // ---- Layer 3: 512 -> 512 (no fp32 out; bf16 hi/lo feeds FC) ----
    gather_vec4<<<gatherBlocks, 256>>>(h2, 512, aggh, aggl);
    {
        dim3 grid(4, gridY);
        dual_gemm_bf16<<<grid, 256, 81920>>>(aggh, aggl, bAh, bAl,
                                             wth + 311296, wtl + 311296,
                                             wth + 573440, wtl + 573440,
                                             b3, (float*)nullptr, bBh, bBl,
                                             N_NODES, 512, 512, 1);
    }

    // ---- FC 512->128 via GEMM (no relu), then LN + ReLU + pool ----
    {
        dim3 grid(1, gridY);
        dual_gemm_bf16<<<grid, 256, 81920>>>(bBh, bBl,
                                             (__nv_bfloat16*)nullptr,
                                             (__nv_bfloat16*)nullptr,
                                             wth + 835584, wtl + 835584,
                                             (__nv_bfloat16*)nullptr,
                                             (__nv_bfloat16*)nullptr,
                                             bfc, h1,
                                             (__nv_bfloat16*)nullptr,
                                             (__nv_bfloat16*)nullptr,
                                             N_NODES, 512, 128, 0);
    }
    zero_kernel<<<128, 256>>>((float4*)pooled, N_GRAPHS * 128 / 4);
    ln_pool<<<(N_NODES + LN_ROWS - 1) / LN_ROWS, 128>>>(
        h1, lng, lnb, batch, x_atom, pooled, N_NODES);
}

// round 9
// speedup vs baseline: 1.3796x; 1.3796x over previous
#include <cuda_runtime.h>
#include <cuda_bf16.h>
#include <cstdint>

#define N_NODES 50000
#define N_EDGES 800000
#define N_GRAPHS 1024

// ---------------- device-global scratch (allocation-free rule) -------------
__device__ float g_z[(size_t)N_NODES * 128];    // FC output
__device__ __nv_bfloat16 g_agg_hi[(size_t)N_NODES * 512];
__device__ __nv_bfloat16 g_agg_lo[(size_t)N_NODES * 512];
__device__ __nv_bfloat16 g_bufA_hi[(size_t)N_NODES * 512];
__device__ __nv_bfloat16 g_bufA_lo[(size_t)N_NODES * 512];
__device__ __nv_bfloat16 g_bufB_hi[(size_t)N_NODES * 512];
__device__ __nv_bfloat16 g_bufB_lo[(size_t)N_NODES * 512];
// transposed weights bf16 hi/lo [M][Kpad]
// W1r:0(256x96) W1o:24576 W2r:49152(512x256) W2o:180224
// W3r:311296(512x512) W3o:573440 Wfc:835584(128x512)  total 901120
__device__ __nv_bfloat16 g_wt_hi[901120];
__device__ __nv_bfloat16 g_wt_lo[901120];
// CSR
__device__ int g_cnt[N_NODES];
__device__ int g_off[N_NODES + 1];
__device__ int g_cur[N_NODES];
__device__ int g_srcs[N_EDGES];
__device__ int g_bsum[64];

// ---------------------------------------------------------------------------
__global__ void zero_kernel(float4* __restrict__ p, int n4) {
    int i = blockIdx.x * blockDim.x + threadIdx.x;
    int stride = gridDim.x * blockDim.x;
    float4 z = make_float4(0.f, 0.f, 0.f, 0.f);
    for (; i < n4; i += stride) p[i] = z;
}

__global__ void zero_int(int* __restrict__ p, int n) {
    int i = blockIdx.x * blockDim.x + threadIdx.x;
    if (i < n) p[i] = 0;
}

// ---------------------------------------------------------------------------
// Fused weight prep: all 7 weights, W [K,M] fp32 -> hi/lo [M,Kpad] transposed
// ---------------------------------------------------------------------------
struct PrepArgs {
    const float* W[7];
    int K[7];
    int M[7];
    int Kpad[7];
    int off[7];
};

__global__ void prep_all(PrepArgs a,
                         __nv_bfloat16* __restrict__ hi,
                         __nv_bfloat16* __restrict__ lo) {
    int seg = blockIdx.y;
    int idx = blockIdx.x * blockDim.x + threadIdx.x;
    int Kpad = a.Kpad[seg];
    if (idx >= a.M[seg] * Kpad) return;
    int n = idx / Kpad, k = idx % Kpad;
    int K = a.K[seg];
    float v = (k < K) ? a.W[seg][(size_t)k * a.M[seg] + n] : 0.f;
    __nv_bfloat16 h = __float2bfloat16(v);
    size_t o = (size_t)a.off[seg] + idx;
    hi[o] = h;
    lo[o] = __float2bfloat16(v - __bfloat162float(h));
}

// x [N,78] fp32 -> hi/lo [N,96] bf16 padded
__global__ void prep_x(const float* __restrict__ x,
                       __nv_bfloat16* __restrict__ hi,
                       __nv_bfloat16* __restrict__ lo) {
    int idx = blockIdx.x * blockDim.x + threadIdx.x;
    if (idx >= N_NODES * 96) return;
    int n = idx / 96, k = idx % 96;
    float v = (k < 78) ? x[(size_t)n * 78 + k] : 0.f;
    __nv_bfloat16 h = __float2bfloat16(v);
    hi[idx] = h;
    lo[idx] = __float2bfloat16(v - __bfloat162float(h));
}

// ---------------------------------------------------------------------------
// CSR build
// ---------------------------------------------------------------------------
__global__ void hist_kernel(const int* __restrict__ ei) {
    int e = blockIdx.x * blockDim.x + threadIdx.x;
    if (e < N_EDGES) atomicAdd(&g_cnt[ei[N_EDGES + e]], 1);
}

__global__ void scan1(void) {
    __shared__ int sm[1024];
    int tid = threadIdx.x;
    int i = blockIdx.x * 1024 + tid;
    int v = (i < N_NODES) ? g_cnt[i] : 0;
    sm[tid] = v;
    __syncthreads();
    for (int o = 1; o < 1024; o <<= 1) {
        int t = (tid >= o) ? sm[tid - o] : 0;
        __syncthreads();
        sm[tid] += t;
        __syncthreads();
    }
    if (i < N_NODES) g_off[i] = sm[tid] - v;
    if (tid == 1023) g_bsum[blockIdx.x] = sm[1023];
}

__global__ void scan2(int nblk) {
    if (threadIdx.x == 0) {
        int run = 0;
        for (int b = 0; b < nblk; ++b) {
            int t = g_bsum[b];
            g_bsum[b] = run;
            run += t;
        }
    }
}

__global__ void scan3(void) {
    int i = blockIdx.x * blockDim.x + threadIdx.x;
    if (i < N_NODES) {
        int o = g_off[i] + g_bsum[i >> 10];
        g_off[i] = o;
        g_cur[i] = o;
    }
    if (i == 0) g_off[N_NODES] = N_EDGES;
}

__global__ void fill_kernel(const int* __restrict__ ei) {
    int e = blockIdx.x * blockDim.x + threadIdx.x;
    if (e >= N_EDGES) return;
    int s = ei[e], t = ei[N_EDGES + e];
    int pos = atomicAdd(&g_cur[t], 1);
    g_srcs[pos] = s;
}

// ---------------------------------------------------------------------------
// CSR gather from fp32 x (layer 1) -> bf16 hi/lo.  Warp per node.
// ---------------------------------------------------------------------------
__global__ void gather78(const float* __restrict__ x,
                         __nv_bfloat16* __restrict__ ahi,
                         __nv_bfloat16* __restrict__ alo) {
    int n = (blockIdx.x * blockDim.x + threadIdx.x) >> 5;
    int lane = threadIdx.x & 31;
    if (n >= N_NODES) return;
    int jb = g_off[n], je = g_off[n + 1];
    float a0 = 0.f, a1 = 0.f, a2 = 0.f;
    for (int j = jb; j < je; ++j) {
        const float* xr = x + (size_t)g_srcs[j] * 78;
        a0 += __ldg(xr + lane);
        a1 += __ldg(xr + lane + 32);
        if (lane < 14) a2 += __ldg(xr + lane + 64);
    }
    size_t base = (size_t)n * 96;
    float vals[3] = {a0, a1, (lane < 14) ? a2 : 0.f};
    #pragma unroll
    for (int i = 0; i < 3; ++i) {
        __nv_bfloat16 h = __float2bfloat16(vals[i]);
        ahi[base + lane + i * 32] = h;
        alo[base + lane + i * 32] = __float2bfloat16(vals[i] - __bfloat162float(h));
    }
}

// CSR gather from bf16 hi/lo feature buffers (layers 2,3) -> bf16 hi/lo.
// val = float(hi) + float(lo); same 4 B/elem traffic as fp32.
__global__ void gather_hilo(const __nv_bfloat16* __restrict__ xhi,
                            const __nv_bfloat16* __restrict__ xlo, int d,
                            __nv_bfloat16* __restrict__ ahi,
                            __nv_bfloat16* __restrict__ alo) {
    int n = (blockIdx.x * blockDim.x + threadIdx.x) >> 5;
    int lane = threadIdx.x & 31;
    if (n >= N_NODES) return;
    int jb = g_off[n], je = g_off[n + 1];
    int ni = d >> 7;                 // 4-elem groups per lane (2 or 4)
    float4 acc[4];
    #pragma unroll
    for (int i = 0; i < 4; ++i) acc[i] = make_float4(0.f, 0.f, 0.f, 0.f);
    for (int j = jb; j < je; ++j) {
        size_t rb = (size_t)g_srcs[j] * d;
        const uint2* hr = (const uint2*)(xhi + rb);
        const uint2* lr = (const uint2*)(xlo + rb);
        #pragma unroll 4
        for (int i = 0; i < ni; ++i) {
            uint2 hv = __ldg(hr + lane + i * 32);
            uint2 lv = __ldg(lr + lane + i * 32);
            float2 h0 = __bfloat1622float2(*(__nv_bfloat162*)&hv.x);
            float2 h1 = __bfloat1622float2(*(__nv_bfloat162*)&hv.y);
            float2 l0 = __bfloat1622float2(*(__nv_bfloat162*)&lv.x);
            float2 l1 = __bfloat1622float2(*(__nv_bfloat162*)&lv.y);
            acc[i].x += h0.x + l0.x;
            acc[i].y += h0.y + l0.y;
            acc[i].z += h1.x + l1.x;
            acc[i].w += h1.y + l1.y;
        }
    }
    for (int i = 0; i < ni; ++i) {
        int c = (lane + i * 32) * 4;
        float4 a = acc[i];
        __nv_bfloat162 h01 = __floats2bfloat162_rn(a.x, a.y);
        __nv_bfloat162 h23 = __floats2bfloat162_rn(a.z, a.w);
        __nv_bfloat162 l01 = __floats2bfloat162_rn(a.x - __bfloat162float(h01.x),
                                                   a.y - __bfloat162float(h01.y));
        __nv_bfloat162 l23 = __floats2bfloat162_rn(a.z - __bfloat162float(h23.x),
                                                   a.w - __bfloat162float(h23.y));
        *(uint2*)(ahi + (size_t)n * d + c) =
            make_uint2(*(unsigned*)&h01, *(unsigned*)&h23);
        *(uint2*)(alo + (size_t)n * d + c) =
            make_uint2(*(unsigned*)&l01, *(unsigned*)&l23);
    }
}

// ---------------------------------------------------------------------------
// mma / ldmatrix / cp.async helpers
// ---------------------------------------------------------------------------
__device__ __forceinline__ void mma_bf16(float* c, const unsigned* a,
                                         unsigned b0, unsigned b1) {
    asm volatile(
        "mma.sync.aligned.m16n8k16.row.col.f32.bf16.bf16.f32 "
        "{%0,%1,%2,%3}, {%4,%5,%6,%7}, {%8,%9}, {%0,%1,%2,%3};"
        : "+f"(c[0]), "+f"(c[1]), "+f"(c[2]), "+f"(c[3])
        : "r"(a[0]), "r"(a[1]), "r"(a[2]), "r"(a[3]), "r"(b0), "r"(b1));
}

__device__ __forceinline__ void ldm_x4(unsigned* r, uint32_t addr) {
    asm volatile(
        "ldmatrix.sync.aligned.m8n8.x4.shared.b16 {%0,%1,%2,%3}, [%4];"
        : "=r"(r[0]), "=r"(r[1]), "=r"(r[2]), "=r"(r[3]) : "r"(addr));
}

__device__ __forceinline__ void ldm_x2(unsigned* r, uint32_t addr) {
    asm volatile(
        "ldmatrix.sync.aligned.m8n8.x2.shared.b16 {%0,%1}, [%2];"
        : "=r"(r[0]), "=r"(r[1]) : "r"(addr));
}

__device__ __forceinline__ void cpa16(uint32_t d, const void* s, int sz) {
    asm volatile("cp.async.cg.shared.global [%0], [%1], 16, %2;"
                 :: "r"(d), "l"(s), "r"(sz) : "memory");
}

// ---------------------------------------------------------------------------
// Dual/single GEMM (bf16 hi/lo 3-term split), cp.async double-buffered.
//   C = act(A1 @ B1 [+ A2 @ B2] + bias),  act = ReLU if do_relu
// Operands bf16 hi/lo [rows][Kpad], K contiguous.  Tiles 128x128, chunk K=32.
// Dynamic smem: 2 stages x (Ah,Al,Bh,Bl) x 128x40 bf16 = 81920 B.
// B fragments via ldmatrix.x2 (80B row stride is conflict-free for 8-row
// loads; 16-row x4 pairing conflicts 2-way -- do NOT pair).
// ---------------------------------------------------------------------------
#define RS 40
#define TILE_B 10240
#define STAGE_B 40960

__global__ __launch_bounds__(256, 2)
void dual_gemm_bf16(const __nv_bfloat16* __restrict__ A1h,
                    const __nv_bfloat16* __restrict__ A1l,
                    const __nv_bfloat16* __restrict__ A2h,
                    const __nv_bfloat16* __restrict__ A2l,
                    const __nv_bfloat16* __restrict__ B1h,
                    const __nv_bfloat16* __restrict__ B1l,
                    const __nv_bfloat16* __restrict__ B2h,
                    const __nv_bfloat16* __restrict__ B2l,
                    const float* __restrict__ bias, float* __restrict__ C,
                    __nv_bfloat16* __restrict__ Chi,
                    __nv_bfloat16* __restrict__ Clo,
                    int N, int Kpad, int M, int do_relu) {
    extern __shared__ __align__(16) char dynsmem[];
    uint32_t ubase = (uint32_t)__cvta_generic_to_shared(dynsmem);

    int tid = threadIdx.x;
    int lane = tid & 31, wid = tid >> 5;
    int wr = wid & 3, wc = wid >> 2;
    int m0w = wr * 32, n0w = wc * 64;
    int gid = lane >> 2, tig = lane & 3;

    int rowBase = blockIdx.y * 128;
    int colBase = blockIdx.x * 128;

    int a_row = (lane & 7) + ((lane >> 3) & 1) * 8;
    int a_koff = (lane >> 4) * 16;
    int b_row = lane & 7;
    int b_koff = ((lane >> 3) & 1) * 16;

    int lr0 = tid >> 2, lc0 = tid & 3;
    int lr1 = (tid + 256) >> 2, lc1 = tid & 3;

    float acc[2][8][4];
    #pragma unroll
    for (int mt = 0; mt < 2; mt++)
        #pragma unroll
        for (int nt = 0; nt < 8; nt++)
            #pragma unroll
            for (int i = 0; i < 4; i++) acc[mt][nt][i] = 0.f;

    const int nch = Kpad >> 5;
    const int npass = (A2h != nullptr) ? 2 : 1;
    const int T = npass * nch;

    auto load_iter = [&](int it, int stage) {
        int pass = (it >= nch) ? 1 : 0;
        int ch = it - pass * nch;
        int k0 = ch << 5;
        const __nv_bfloat16* AH = pass ? A2h : A1h;
        const __nv_bfloat16* AL = pass ? A2l : A1l;
        const __nv_bfloat16* BH = pass ? B2h : B1h;
        const __nv_bfloat16* BL = pass ? B2l : B1l;
        uint32_t sb = ubase + stage * STAGE_B;
        {
            int gr0 = rowBase + lr0;
            int gr1 = rowBase + lr1;
            int g0 = (gr0 < N) ? gr0 : 0, s0 = (gr0 < N) ? 16 : 0;
            int g1 = (gr1 < N) ? gr1 : 0, s1 = (gr1 < N) ? 16 : 0;
            size_t o0 = (size_t)g0 * Kpad + k0 + lc0 * 8;
            size_t o1 = (size_t)g1 * Kpad + k0 + lc1 * 8;
            cpa16(sb + lr0 * 80 + lc0 * 16, AH + o0, s0);
            cpa16(sb + lr1 * 80 + lc1 * 16, AH + o1, s1);
            cpa16(sb + TILE_B + lr0 * 80 + lc0 * 16, AL + o0, s0);
            cpa16(sb + TILE_B + lr1 * 80 + lc1 * 16, AL + o1, s1);
        }
        {
            size_t o0 = (size_t)(colBase + lr0) * Kpad + k0 + lc0 * 8;
            size_t o1 = (size_t)(colBase + lr1) * Kpad + k0 + lc1 * 8;
            cpa16(sb + 2 * TILE_B + lr0 * 80 + lc0 * 16, BH + o0, 16);
            cpa16(sb + 2 * TILE_B + lr1 * 80 + lc1 * 16, BH + o1, 16);
            cpa16(sb + 3 * TILE_B + lr0 * 80 + lc0 * 16, BL + o0, 16);
            cpa16(sb + 3 * TILE_B + lr1 * 80 + lc1 * 16, BL + o1, 16);
        }
        asm volatile("cp.async.commit_group;" ::: "memory");
    };

    load_iter(0, 0);

    #pragma unroll 1
    for (int it = 0; it < T; ++it) {
        if (it + 1 < T) {
            load_iter(it + 1, (it + 1) & 1);
            asm volatile("cp.async.wait_group 1;" ::: "memory");
        } else {
            asm volatile("cp.async.wait_group 0;" ::: "memory");
        }
        __syncthreads();

        uint32_t sb = ubase + (it & 1) * STAGE_B;
        uint32_t uAh = sb, uAl = sb + TILE_B;
        uint32_t uBh = sb + 2 * TILE_B, uBl = sb + 3 * TILE_B;

        #pragma unroll
        for (int ks = 0; ks < 2; ++ks) {
            int kb = ks * 32;
            unsigned ah[2][4], al[2][4];
            #pragma unroll
            for (int mt = 0; mt < 2; mt++) {
                uint32_t ao = (uint32_t)((m0w + mt * 16 + a_row) * 80
                                         + kb + a_koff);
                ldm_x4(ah[mt], uAh + ao);
                ldm_x4(al[mt], uAl + ao);
            }
            #pragma unroll
            for (int nt = 0; nt < 8; nt++) {
                uint32_t bo = (uint32_t)((n0w + nt * 8 + b_row) * 80
                                         + kb + b_koff);
                unsigned bh[2], bl[2];
                ldm_x2(bh, uBh + bo);
                ldm_x2(bl, uBl + bo);
                #pragma unroll
                for (int mt = 0; mt < 2; mt++) {
                    mma_bf16(acc[mt][nt], ah[mt], bh[0], bh[1]);
                    mma_bf16(acc[mt][nt], al[mt], bh[0], bh[1]);
                    mma_bf16(acc[mt][nt], ah[mt], bl[0], bl[1]);
                }
            }
        }
        __syncthreads();
    }

    // ---- Epilogue ----
    #pragma unroll
    for (int mt = 0; mt < 2; mt++) {
        #pragma unroll
        for (int nt = 0; nt < 8; nt++) {
            int r = rowBase + m0w + mt * 16 + gid;
            int c = colBase + n0w + nt * 8 + tig * 2;
            float b0v = bias[c], b1v = bias[c + 1];
            #pragma unroll
            for (int half = 0; half < 2; ++half) {
                int rr = r + half * 8;
                if (rr >= N) continue;
                float v0 = acc[mt][nt][2 * half + 0] + b0v;
                float v1 = acc[mt][nt][2 * half + 1] + b1v;
                if (do_relu) {
                    v0 = v0 > 0.f ? v0 : 0.f;
                    v1 = v1 > 0.f ? v1 : 0.f;
                }
                size_t o = (size_t)rr * M + c;
                if (C) {
                    C[o] = v0;
                    C[o + 1] = v1;
                }
                if (Chi) {
                    __nv_bfloat162 hh = __floats2bfloat162_rn(v0, v1);
                    __nv_bfloat162 ll = __floats2bfloat162_rn(
                        v0 - __bfloat162float(hh.x), v1 - __bfloat162float(hh.y));
                    *(unsigned*)(Chi + o) = *(unsigned*)&hh;
                    *(unsigned*)(Clo + o) = *(unsigned*)&ll;
                }
            }
        }
    }
}

// ---------------------------------------------------------------------------
// LayerNorm(128) + ReLU + graph pooling over precomputed z = fc(h3).
// ---------------------------------------------------------------------------
#define LN_ROWS 16

__global__ __launch_bounds__(128)
void ln_pool(const float* __restrict__ z, const float* __restrict__ lng,
             const float* __restrict__ lnb, const int* __restrict__ batch,
             float* __restrict__ xa, float* __restrict__ pooled, int N) {
    __shared__ float ws[4], ws2[4];
    int c = threadIdx.x;
    int lane = c & 31;
    int wid = c >> 5;
    int r0 = blockIdx.x * LN_ROWS;
    int nr = min(LN_ROWS, N - r0);

    float g = lng[c], b = lnb[c];
    float pacc = 0.f;
    int curg = -1;
    for (int r = 0; r < nr; ++r) {
        float v = z[(size_t)(r0 + r) * 128 + c];
        float s = v, s2 = v * v;
        #pragma unroll
        for (int o = 16; o > 0; o >>= 1) {
            s  += __shfl_xor_sync(0xffffffffu, s, o);
            s2 += __shfl_xor_sync(0xffffffffu, s2, o);
        }
        __syncthreads();
        if (lane == 0) { ws[wid] = s; ws2[wid] = s2; }
        __syncthreads();
        float sum = ws[0] + ws[1] + ws[2] + ws[3];
        float sum2 = ws2[0] + ws2[1] + ws2[2] + ws2[3];
        float mu = sum * (1.f / 128.f);
        float var = sum2 * (1.f / 128.f) - mu * mu;
        float zz = (v - mu) * rsqrtf(var + 1e-5f) * g + b;
        float relu = zz > 0.f ? zz : 0.f;
        xa[(size_t)(r0 + r) * 128 + c] = relu;

        int gb = batch[r0 + r];
        if (gb != curg) {
            if (curg >= 0) atomicAdd(&pooled[(size_t)curg * 128 + c], pacc);
            curg = gb;
            pacc = 0.f;
        }
        pacc += relu;
    }
    if (curg >= 0) atomicAdd(&pooled[(size_t)curg * 128 + c], pacc);
}

// ---------------------------------------------------------------------------
// Launch
// ---------------------------------------------------------------------------
extern "C" void kernel_launch(void* const* d_in, const int* in_sizes, int n_in,
                              void* d_out, int out_size) {
    const float* x     = (const float*)d_in[0];
    const int*   ei    = (const int*)d_in[1];
    const int*   batch = (const int*)d_in[2];
    const float* W1r = (const float*)d_in[3];
    const float* b1  = (const float*)d_in[4];
    const float* W1o = (const float*)d_in[5];
    const float* W2r = (const float*)d_in[6];
    const float* b2  = (const float*)d_in[7];
    const float* W2o = (const float*)d_in[8];
    const float* W3r = (const float*)d_in[9];
    const float* b3  = (const float*)d_in[10];
    const float* W3o = (const float*)d_in[11];
    const float* Wfc = (const float*)d_in[12];
    const float* bfc = (const float*)d_in[13];
    const float* lng = (const float*)d_in[14];
    const float* lnb = (const float*)d_in[15];

    float* out = (float*)d_out;
    float* x_atom = out;
    float* pooled = out + (size_t)N_NODES * 128;

    float* zbuf;
    __nv_bfloat16 *aggh, *aggl, *bAh, *bAl, *bBh, *bBl, *wth, *wtl;
    cudaGetSymbolAddress((void**)&zbuf, g_z);
    cudaGetSymbolAddress((void**)&aggh, g_agg_hi);
    cudaGetSymbolAddress((void**)&aggl, g_agg_lo);
    cudaGetSymbolAddress((void**)&bAh, g_bufA_hi);
    cudaGetSymbolAddress((void**)&bAl, g_bufA_lo);
    cudaGetSymbolAddress((void**)&bBh, g_bufB_hi);
    cudaGetSymbolAddress((void**)&bBl, g_bufB_lo);
    cudaGetSymbolAddress((void**)&wth, g_wt_hi);
    cudaGetSymbolAddress((void**)&wtl, g_wt_lo);

    cudaFuncSetAttribute(dual_gemm_bf16,
                         cudaFuncAttributeMaxDynamicSharedMemorySize, 81920);

    const int gridY = (N_NODES + 127) / 128;
    const int gatherBlocks = (N_NODES * 32 + 255) / 256;

    // ---- Weight prep (single fused launch) ----
    {
        PrepArgs pa;
        pa.W[0] = W1r; pa.K[0] = 78;  pa.M[0] = 256; pa.Kpad[0] = 96;  pa.off[0] = 0;
        pa.W[1] = W1o; pa.K[1] = 78;  pa.M[1] = 256; pa.Kpad[1] = 96;  pa.off[1] = 24576;
        pa.W[2] = W2r; pa.K[2] = 256; pa.M[2] = 512; pa.Kpad[2] = 256; pa.off[2] = 49152;
        pa.W[3] = W2o; pa.K[3] = 256; pa.M[3] = 512; pa.Kpad[3] = 256; pa.off[3] = 180224;
        pa.W[4] = W3r; pa.K[4] = 512; pa.M[4] = 512; pa.Kpad[4] = 512; pa.off[4] = 311296;
        pa.W[5] = W3o; pa.K[5] = 512; pa.M[5] = 512; pa.Kpad[5] = 512; pa.off[5] = 573440;
        pa.W[6] = Wfc; pa.K[6] = 512; pa.M[6] = 128; pa.Kpad[6] = 512; pa.off[6] = 835584;
        dim3 grid((512 * 512 + 255) / 256, 7);
        prep_all<<<grid, 256>>>(pa, wth, wtl);
    }
    prep_x<<<(N_NODES * 96 + 255) / 256, 256>>>(x, bAh, bAl);

    // ---- CSR build ----
    {
        int* pcnt; cudaGetSymbolAddress((void**)&pcnt, g_cnt);
        zero_int<<<(N_NODES + 255) / 256, 256>>>(pcnt, N_NODES);
    }
    hist_kernel<<<(N_EDGES + 255) / 256, 256>>>(ei);
    scan1<<<(N_NODES + 1023) / 1024, 1024>>>();
    scan2<<<1, 32>>>((N_NODES + 1023) / 1024);
    scan3<<<(N_NODES + 255) / 256, 256>>>();
    fill_kernel<<<(N_EDGES + 255) / 256, 256>>>(ei);

    // ---- Layer 1: 78 -> 256 (out: h1 as bf16 hi/lo only) ----
    gather78<<<gatherBlocks, 256>>>(x, aggh, aggl);
    {
        dim3 grid(2, gridY);
        dual_gemm_bf16<<<grid, 256, 81920>>>(aggh, aggl, bAh, bAl,
                                             wth + 0, wtl + 0,
                                             wth + 24576, wtl + 24576,
                                             b1, (float*)nullptr, bBh, bBl,
                                             N_NODES, 96, 256, 1);
    }

    // ---- Layer 2: 256 -> 512 (gather reads h1 hi/lo) ----
    gather_hilo<<<gatherBlocks, 256>>>(bBh, bBl, 256, aggh, aggl);
    {
        dim3 grid(4, gridY);
        dual_gemm_bf16<<<grid, 256, 81920>>>(aggh, aggl, bBh, bBl,
                                             wth + 49152, wtl + 49152,
                                             wth + 180224, wtl + 180224,
                                             b2, (float*)nullptr, bAh, bAl,
                                             N_NODES, 256, 512, 1);
    }

    // ---- Layer 3: 512 -> 512 (gather reads h2 hi/lo) ----
    gather_hilo<<<gatherBlocks, 256>>>(bAh, bAl, 512, aggh, aggl);
    {
        dim3 grid(4, gridY);
        dual_gemm_bf16<<<grid, 256, 81920>>>(aggh, aggl, bAh, bAl,
                                             wth + 311296, wtl + 311296,
                                             wth + 573440, wtl + 573440,
                                             b3, (float*)nullptr, bBh, bBl,
                                             N_NODES, 512, 512, 1);
    }

    // ---- FC 512->128 via GEMM (no relu), then LN + ReLU + pool ----
    {
        dim3 grid(1, gridY);
        dual_gemm_bf16<<<grid, 256, 81920>>>(bBh, bBl,
                                             (__nv_bfloat16*)nullptr,
                                             (__nv_bfloat16*)nullptr,
                                             wth + 835584, wtl + 835584,
                                             (__nv_bfloat16*)nullptr,
                                             (__nv_bfloat16*)nullptr,
                                             bfc, zbuf,
                                             (__nv_bfloat16*)nullptr,
                                             (__nv_bfloat16*)nullptr,
                                             N_NODES, 512, 128, 0);
    }
    zero_kernel<<<128, 256>>>((float4*)pooled, N_GRAPHS * 128 / 4);
    ln_pool<<<(N_NODES + LN_ROWS - 1) / LN_ROWS, 128>>>(
        zbuf, lng, lnb, batch, x_atom, pooled, N_NODES);
}

// round 10
// speedup vs baseline: 1.4945x; 1.0833x over previous
#include <cuda_runtime.h>
#include <cuda_bf16.h>
#include <cstdint>

#define N_NODES 50000
#define N_EDGES 800000
#define N_GRAPHS 1024

// ---------------- device-global scratch (allocation-free rule) -------------
__device__ float g_h1[(size_t)N_NODES * 256];   // also reused for FC z output
__device__ float g_h2[(size_t)N_NODES * 512];
__device__ __nv_bfloat16 g_agg_hi[(size_t)N_NODES * 512];
__device__ __nv_bfloat16 g_agg_lo[(size_t)N_NODES * 512];
__device__ __nv_bfloat16 g_bufA_hi[(size_t)N_NODES * 512];
__device__ __nv_bfloat16 g_bufA_lo[(size_t)N_NODES * 512];
__device__ __nv_bfloat16 g_bufB_hi[(size_t)N_NODES * 512];
__device__ __nv_bfloat16 g_bufB_lo[(size_t)N_NODES * 512];
// transposed weights bf16 hi/lo [M][Kpad]
// W1r:0(256x96) W1o:24576 W2r:49152(512x256) W2o:180224
// W3r:311296(512x512) W3o:573440 Wfc:835584(128x512)  total 901120
__device__ __nv_bfloat16 g_wt_hi[901120];
__device__ __nv_bfloat16 g_wt_lo[901120];
// CSR
__device__ int g_cnt[N_NODES];
__device__ int g_off[N_NODES + 1];
__device__ int g_cur[N_NODES];
__device__ int g_srcs[N_EDGES];
__device__ int g_bsum[64];

// ---------------------------------------------------------------------------
__global__ void zero_kernel(float4* __restrict__ p, int n4) {
    int i = blockIdx.x * blockDim.x + threadIdx.x;
    int stride = gridDim.x * blockDim.x;
    float4 z = make_float4(0.f, 0.f, 0.f, 0.f);
    for (; i < n4; i += stride) p[i] = z;
}

__global__ void zero_int(int* __restrict__ p, int n) {
    int i = blockIdx.x * blockDim.x + threadIdx.x;
    if (i < n) p[i] = 0;
}

// ---------------------------------------------------------------------------
// Fused weight prep: all 7 weights, W [K,M] fp32 -> hi/lo [M,Kpad] transposed
// ---------------------------------------------------------------------------
struct PrepArgs {
    const float* W[7];
    int K[7];
    int M[7];
    int Kpad[7];
    int off[7];
};

__global__ void prep_all(PrepArgs a,
                         __nv_bfloat16* __restrict__ hi,
                         __nv_bfloat16* __restrict__ lo) {
    int seg = blockIdx.y;
    int idx = blockIdx.x * blockDim.x + threadIdx.x;
    int Kpad = a.Kpad[seg];
    if (idx >= a.M[seg] * Kpad) return;
    int n = idx / Kpad, k = idx % Kpad;
    int K = a.K[seg];
    float v = (k < K) ? a.W[seg][(size_t)k * a.M[seg] + n] : 0.f;
    __nv_bfloat16 h = __float2bfloat16(v);
    size_t o = (size_t)a.off[seg] + idx;
    hi[o] = h;
    lo[o] = __float2bfloat16(v - __bfloat162float(h));
}

// x [N,78] fp32 -> hi/lo [N,96] bf16 padded
__global__ void prep_x(const float* __restrict__ x,
                       __nv_bfloat16* __restrict__ hi,
                       __nv_bfloat16* __restrict__ lo) {
    int idx = blockIdx.x * blockDim.x + threadIdx.x;
    if (idx >= N_NODES * 96) return;
    int n = idx / 96, k = idx % 96;
    float v = (k < 78) ? x[(size_t)n * 78 + k] : 0.f;
    __nv_bfloat16 h = __float2bfloat16(v);
    hi[idx] = h;
    lo[idx] = __float2bfloat16(v - __bfloat162float(h));
}

// ---------------------------------------------------------------------------
// CSR build
// ---------------------------------------------------------------------------
__global__ void hist_kernel(const int* __restrict__ ei) {
    int e = blockIdx.x * blockDim.x + threadIdx.x;
    if (e < N_EDGES) atomicAdd(&g_cnt[ei[N_EDGES + e]], 1);
}

__global__ void scan1(void) {
    __shared__ int sm[1024];
    int tid = threadIdx.x;
    int i = blockIdx.x * 1024 + tid;
    int v = (i < N_NODES) ? g_cnt[i] : 0;
    sm[tid] = v;
    __syncthreads();
    for (int o = 1; o < 1024; o <<= 1) {
        int t = (tid >= o) ? sm[tid - o] : 0;
        __syncthreads();
        sm[tid] += t;
        __syncthreads();
    }
    if (i < N_NODES) g_off[i] = sm[tid] - v;
    if (tid == 1023) g_bsum[blockIdx.x] = sm[1023];
}

__global__ void scan2(int nblk) {
    if (threadIdx.x == 0) {
        int run = 0;
        for (int b = 0; b < nblk; ++b) {
            int t = g_bsum[b];
            g_bsum[b] = run;
            run += t;
        }
    }
}

__global__ void scan3(void) {
    int i = blockIdx.x * blockDim.x + threadIdx.x;
    if (i < N_NODES) {
        int o = g_off[i] + g_bsum[i >> 10];
        g_off[i] = o;
        g_cur[i] = o;
    }
    if (i == 0) g_off[N_NODES] = N_EDGES;
}

__global__ void fill_kernel(const int* __restrict__ ei) {
    int e = blockIdx.x * blockDim.x + threadIdx.x;
    if (e >= N_EDGES) return;
    int s = ei[e], t = ei[N_EDGES + e];
    int pos = atomicAdd(&g_cur[t], 1);
    g_srcs[pos] = s;
}

// ---------------------------------------------------------------------------
// CSR gather -> bf16 hi/lo.  Warp per node.  Single fp32 LDG.128 stream.
// ---------------------------------------------------------------------------
__global__ void gather78(const float* __restrict__ x,
                         __nv_bfloat16* __restrict__ ahi,
                         __nv_bfloat16* __restrict__ alo) {
    int n = (blockIdx.x * blockDim.x + threadIdx.x) >> 5;
    int lane = threadIdx.x & 31;
    if (n >= N_NODES) return;
    int jb = g_off[n], je = g_off[n + 1];
    float a0 = 0.f, a1 = 0.f, a2 = 0.f;
    for (int j = jb; j < je; ++j) {
        const float* xr = x + (size_t)g_srcs[j] * 78;
        a0 += __ldg(xr + lane);
        a1 += __ldg(xr + lane + 32);
        if (lane < 14) a2 += __ldg(xr + lane + 64);
    }
    size_t base = (size_t)n * 96;
    float vals[3] = {a0, a1, (lane < 14) ? a2 : 0.f};
    #pragma unroll
    for (int i = 0; i < 3; ++i) {
        __nv_bfloat16 h = __float2bfloat16(vals[i]);
        ahi[base + lane + i * 32] = h;
        alo[base + lane + i * 32] = __float2bfloat16(vals[i] - __bfloat162float(h));
    }
}

__global__ void gather_vec4(const float* __restrict__ x, int d,
                            __nv_bfloat16* __restrict__ ahi,
                            __nv_bfloat16* __restrict__ alo) {
    int n = (blockIdx.x * blockDim.x + threadIdx.x) >> 5;
    int lane = threadIdx.x & 31;
    if (n >= N_NODES) return;
    int jb = g_off[n], je = g_off[n + 1];
    int ni = d >> 7;
    float4 acc[4];
    #pragma unroll
    for (int i = 0; i < 4; ++i) acc[i] = make_float4(0.f, 0.f, 0.f, 0.f);
    for (int j = jb; j < je; ++j) {
        const float4* xr = (const float4*)(x + (size_t)g_srcs[j] * d);
        #pragma unroll 4
        for (int i = 0; i < ni; ++i) {
            float4 v = __ldg(xr + lane + i * 32);
            acc[i].x += v.x; acc[i].y += v.y; acc[i].z += v.z; acc[i].w += v.w;
        }
    }
    for (int i = 0; i < ni; ++i) {
        int c = (lane + i * 32) * 4;
        float4 a = acc[i];
        __nv_bfloat162 h01 = __floats2bfloat162_rn(a.x, a.y);
        __nv_bfloat162 h23 = __floats2bfloat162_rn(a.z, a.w);
        __nv_bfloat162 l01 = __floats2bfloat162_rn(a.x - __bfloat162float(h01.x),
                                                   a.y - __bfloat162float(h01.y));
        __nv_bfloat162 l23 = __floats2bfloat162_rn(a.z - __bfloat162float(h23.x),
                                                   a.w - __bfloat162float(h23.y));
        *(uint2*)(ahi + (size_t)n * d + c) =
            make_uint2(*(unsigned*)&h01, *(unsigned*)&h23);
        *(uint2*)(alo + (size_t)n * d + c) =
            make_uint2(*(unsigned*)&l01, *(unsigned*)&l23);
    }
}

// ---------------------------------------------------------------------------
// mma / ldmatrix / cp.async helpers
// ---------------------------------------------------------------------------
__device__ __forceinline__ void mma_bf16(float* c, const unsigned* a,
                                         unsigned b0, unsigned b1) {
    asm volatile(
        "mma.sync.aligned.m16n8k16.row.col.f32.bf16.bf16.f32 "
        "{%0,%1,%2,%3}, {%4,%5,%6,%7}, {%8,%9}, {%0,%1,%2,%3};"
        : "+f"(c[0]), "+f"(c[1]), "+f"(c[2]), "+f"(c[3])
        : "r"(a[0]), "r"(a[1]), "r"(a[2]), "r"(a[3]), "r"(b0), "r"(b1));
}

__device__ __forceinline__ void ldm_x4(unsigned* r, uint32_t addr) {
    asm volatile(
        "ldmatrix.sync.aligned.m8n8.x4.shared.b16 {%0,%1,%2,%3}, [%4];"
        : "=r"(r[0]), "=r"(r[1]), "=r"(r[2]), "=r"(r[3]) : "r"(addr));
}

__device__ __forceinline__ void ldm_x2(unsigned* r, uint32_t addr) {
    asm volatile(
        "ldmatrix.sync.aligned.m8n8.x2.shared.b16 {%0,%1}, [%2];"
        : "=r"(r[0]), "=r"(r[1]) : "r"(addr));
}

__device__ __forceinline__ void cpa16(uint32_t d, const void* s, int sz) {
    asm volatile("cp.async.cg.shared.global [%0], [%1], 16, %2;"
                 :: "r"(d), "l"(s), "r"(sz) : "memory");
}

// ---------------------------------------------------------------------------
// Dual/single GEMM (bf16 hi/lo 3-term split), cp.async double-buffered.
//   C = act(A1 @ B1 [+ A2 @ B2] + bias),  act = ReLU if do_relu
// Operands bf16 hi/lo [rows][Kpad], K contiguous.  Tiles 128x128, chunk K=32.
// Dynamic smem: 2 stages x (Ah,Al,Bh,Bl) x 128x40 bf16 = 81920 B.
// B fragments via ldmatrix.x2 (80B row stride conflict-free for 8-row loads;
// 16-row x4 pairing conflicts 2-way -- do NOT pair).
// ---------------------------------------------------------------------------
#define RS 40
#define TILE_B 10240
#define STAGE_B 40960

__global__ __launch_bounds__(256, 2)
void dual_gemm_bf16(const __nv_bfloat16* __restrict__ A1h,
                    const __nv_bfloat16* __restrict__ A1l,
                    const __nv_bfloat16* __restrict__ A2h,
                    const __nv_bfloat16* __restrict__ A2l,
                    const __nv_bfloat16* __restrict__ B1h,
                    const __nv_bfloat16* __restrict__ B1l,
                    const __nv_bfloat16* __restrict__ B2h,
                    const __nv_bfloat16* __restrict__ B2l,
                    const float* __restrict__ bias, float* __restrict__ C,
                    __nv_bfloat16* __restrict__ Chi,
                    __nv_bfloat16* __restrict__ Clo,
                    int N, int Kpad, int M, int do_relu) {
    extern __shared__ __align__(16) char dynsmem[];
    uint32_t ubase = (uint32_t)__cvta_generic_to_shared(dynsmem);

    int tid = threadIdx.x;
    int lane = tid & 31, wid = tid >> 5;
    int wr = wid & 3, wc = wid >> 2;
    int m0w = wr * 32, n0w = wc * 64;
    int gid = lane >> 2, tig = lane & 3;

    int rowBase = blockIdx.y * 128;
    int colBase = blockIdx.x * 128;

    int a_row = (lane & 7) + ((lane >> 3) & 1) * 8;
    int a_koff = (lane >> 4) * 16;
    int b_row = lane & 7;
    int b_koff = ((lane >> 3) & 1) * 16;

    int lr0 = tid >> 2, lc0 = tid & 3;
    int lr1 = (tid + 256) >> 2, lc1 = tid & 3;

    float acc[2][8][4];
    #pragma unroll
    for (int mt = 0; mt < 2; mt++)
        #pragma unroll
        for (int nt = 0; nt < 8; nt++)
            #pragma unroll
            for (int i = 0; i < 4; i++) acc[mt][nt][i] = 0.f;

    const int nch = Kpad >> 5;
    const int npass = (A2h != nullptr) ? 2 : 1;
    const int T = npass * nch;

    auto load_iter = [&](int it, int stage) {
        int pass = (it >= nch) ? 1 : 0;
        int ch = it - pass * nch;
        int k0 = ch << 5;
        const __nv_bfloat16* AH = pass ? A2h : A1h;
        const __nv_bfloat16* AL = pass ? A2l : A1l;
        const __nv_bfloat16* BH = pass ? B2h : B1h;
        const __nv_bfloat16* BL = pass ? B2l : B1l;
        uint32_t sb = ubase + stage * STAGE_B;
        {
            int gr0 = rowBase + lr0;
            int gr1 = rowBase + lr1;
            int g0 = (gr0 < N) ? gr0 : 0, s0 = (gr0 < N) ? 16 : 0;
            int g1 = (gr1 < N) ? gr1 : 0, s1 = (gr1 < N) ? 16 : 0;
            size_t o0 = (size_t)g0 * Kpad + k0 + lc0 * 8;
            size_t o1 = (size_t)g1 * Kpad + k0 + lc1 * 8;
            cpa16(sb + lr0 * 80 + lc0 * 16, AH + o0, s0);
            cpa16(sb + lr1 * 80 + lc1 * 16, AH + o1, s1);
            cpa16(sb + TILE_B + lr0 * 80 + lc0 * 16, AL + o0, s0);
            cpa16(sb + TILE_B + lr1 * 80 + lc1 * 16, AL + o1, s1);
        }
        {
            size_t o0 = (size_t)(colBase + lr0) * Kpad + k0 + lc0 * 8;
            size_t o1 = (size_t)(colBase + lr1) * Kpad + k0 + lc1 * 8;
            cpa16(sb + 2 * TILE_B + lr0 * 80 + lc0 * 16, BH + o0, 16);
            cpa16(sb + 2 * TILE_B + lr1 * 80 + lc1 * 16, BH + o1, 16);
            cpa16(sb + 3 * TILE_B + lr0 * 80 + lc0 * 16, BL + o0, 16);
            cpa16(sb + 3 * TILE_B + lr1 * 80 + lc1 * 16, BL + o1, 16);
        }
        asm volatile("cp.async.commit_group;" ::: "memory");
    };

    load_iter(0, 0);

    #pragma unroll 1
    for (int it = 0; it < T; ++it) {
        if (it + 1 < T) {
            load_iter(it + 1, (it + 1) & 1);
            asm volatile("cp.async.wait_group 1;" ::: "memory");
        } else {
            asm volatile("cp.async.wait_group 0;" ::: "memory");
        }
        __syncthreads();

        uint32_t sb = ubase + (it & 1) * STAGE_B;
        uint32_t uAh = sb, uAl = sb + TILE_B;
        uint32_t uBh = sb + 2 * TILE_B, uBl = sb + 3 * TILE_B;

        #pragma unroll
        for (int ks = 0; ks < 2; ++ks) {
            int kb = ks * 32;
            unsigned ah[2][4], al[2][4];
            #pragma unroll
            for (int mt = 0; mt < 2; mt++) {
                uint32_t ao = (uint32_t)((m0w + mt * 16 + a_row) * 80
                                         + kb + a_koff);
                ldm_x4(ah[mt], uAh + ao);
                ldm_x4(al[mt], uAl + ao);
            }
            #pragma unroll
            for (int nt = 0; nt < 8; nt++) {
                uint32_t bo = (uint32_t)((n0w + nt * 8 + b_row) * 80
                                         + kb + b_koff);
                unsigned bh[2], bl[2];
                ldm_x2(bh, uBh + bo);
                ldm_x2(bl, uBl + bo);
                #pragma unroll
                for (int mt = 0; mt < 2; mt++) {
                    mma_bf16(acc[mt][nt], ah[mt], bh[0], bh[1]);
                    mma_bf16(acc[mt][nt], al[mt], bh[0], bh[1]);
                    mma_bf16(acc[mt][nt], ah[mt], bl[0], bl[1]);
                }
            }
        }
        __syncthreads();
    }

    // ---- Epilogue ----
    #pragma unroll
    for (int mt = 0; mt < 2; mt++) {
        #pragma unroll
        for (int nt = 0; nt < 8; nt++) {
            int r = rowBase + m0w + mt * 16 + gid;
            int c = colBase + n0w + nt * 8 + tig * 2;
            float b0v = bias[c], b1v = bias[c + 1];
            #pragma unroll
            for (int half = 0; half < 2; ++half) {
                int rr = r + half * 8;
                if (rr >= N) continue;
                float v0 = acc[mt][nt][2 * half + 0] + b0v;
                float v1 = acc[mt][nt][2 * half + 1] + b1v;
                if (do_relu) {
                    v0 = v0 > 0.f ? v0 : 0.f;
                    v1 = v1 > 0.f ? v1 : 0.f;
                }
                size_t o = (size_t)rr * M + c;
                if (C) {
                    C[o] = v0;
                    C[o + 1] = v1;
                }
                if (Chi) {
                    __nv_bfloat162 hh = __floats2bfloat162_rn(v0, v1);
                    __nv_bfloat162 ll = __floats2bfloat162_rn(
                        v0 - __bfloat162float(hh.x), v1 - __bfloat162float(hh.y));
                    *(unsigned*)(Chi + o) = *(unsigned*)&hh;
                    *(unsigned*)(Clo + o) = *(unsigned*)&ll;
                }
            }
        }
    }
}

// ---------------------------------------------------------------------------
// LayerNorm(128) + ReLU + graph pooling over precomputed z = fc(h3).
// ---------------------------------------------------------------------------
#define LN_ROWS 16

__global__ __launch_bounds__(128)
void ln_pool(const float* __restrict__ z, const float* __restrict__ lng,
             const float* __restrict__ lnb, const int* __restrict__ batch,
             float* __restrict__ xa, float* __restrict__ pooled, int N) {
    __shared__ float ws[4], ws2[4];
    int c = threadIdx.x;
    int lane = c & 31;
    int wid = c >> 5;
    int r0 = blockIdx.x * LN_ROWS;
    int nr = min(LN_ROWS, N - r0);

    float g = lng[c], b = lnb[c];
    float pacc = 0.f;
    int curg = -1;
    for (int r = 0; r < nr; ++r) {
        float v = z[(size_t)(r0 + r) * 128 + c];
        float s = v, s2 = v * v;
        #pragma unroll
        for (int o = 16; o > 0; o >>= 1) {
            s  += __shfl_xor_sync(0xffffffffu, s, o);
            s2 += __shfl_xor_sync(0xffffffffu, s2, o);
        }
        __syncthreads();
        if (lane == 0) { ws[wid] = s; ws2[wid] = s2; }
        __syncthreads();
        float sum = ws[0] + ws[1] + ws[2] + ws[3];
        float sum2 = ws2[0] + ws2[1] + ws2[2] + ws2[3];
        float mu = sum * (1.f / 128.f);
        float var = sum2 * (1.f / 128.f) - mu * mu;
        float zz = (v - mu) * rsqrtf(var + 1e-5f) * g + b;
        float relu = zz > 0.f ? zz : 0.f;
        xa[(size_t)(r0 + r) * 128 + c] = relu;

        int gb = batch[r0 + r];
        if (gb != curg) {
            if (curg >= 0) atomicAdd(&pooled[(size_t)curg * 128 + c], pacc);
            curg = gb;
            pacc = 0.f;
        }
        pacc += relu;
    }
    if (curg >= 0) atomicAdd(&pooled[(size_t)curg * 128 + c], pacc);
}

// ---------------------------------------------------------------------------
// Launch
// ---------------------------------------------------------------------------
extern "C" void kernel_launch(void* const* d_in, const int* in_sizes, int n_in,
                              void* d_out, int out_size) {
    const float* x     = (const float*)d_in[0];
    const int*   ei    = (const int*)d_in[1];
    const int*   batch = (const int*)d_in[2];
    const float* W1r = (const float*)d_in[3];
    const float* b1  = (const float*)d_in[4];
    const float* W1o = (const float*)d_in[5];
    const float* W2r = (const float*)d_in[6];
    const float* b2  = (const float*)d_in[7];
    const float* W2o = (const float*)d_in[8];
    const float* W3r = (const float*)d_in[9];
    const float* b3  = (const float*)d_in[10];
    const float* W3o = (const float*)d_in[11];
    const float* Wfc = (const float*)d_in[12];
    const float* bfc = (const float*)d_in[13];
    const float* lng = (const float*)d_in[14];
    const float* lnb = (const float*)d_in[15];

    float* out = (float*)d_out;
    float* x_atom = out;
    float* pooled = out + (size_t)N_NODES * 128;

    float *h1, *h2;
    __nv_bfloat16 *aggh, *aggl, *bAh, *bAl, *bBh, *bBl, *wth, *wtl;
    cudaGetSymbolAddress((void**)&h1, g_h1);
    cudaGetSymbolAddress((void**)&h2, g_h2);
    cudaGetSymbolAddress((void**)&aggh, g_agg_hi);
    cudaGetSymbolAddress((void**)&aggl, g_agg_lo);
    cudaGetSymbolAddress((void**)&bAh, g_bufA_hi);
    cudaGetSymbolAddress((void**)&bAl, g_bufA_lo);
    cudaGetSymbolAddress((void**)&bBh, g_bufB_hi);
    cudaGetSymbolAddress((void**)&bBl, g_bufB_lo);
    cudaGetSymbolAddress((void**)&wth, g_wt_hi);
    cudaGetSymbolAddress((void**)&wtl, g_wt_lo);

    cudaFuncSetAttribute(dual_gemm_bf16,
                         cudaFuncAttributeMaxDynamicSharedMemorySize, 81920);

    const int gridY = (N_NODES + 127) / 128;
    const int gatherBlocks = (N_NODES * 32 + 255) / 256;

    // ---- Weight prep (single fused launch) ----
    {
        PrepArgs pa;
        pa.W[0] = W1r; pa.K[0] = 78;  pa.M[0] = 256; pa.Kpad[0] = 96;  pa.off[0] = 0;
        pa.W[1] = W1o; pa.K[1] = 78;  pa.M[1] = 256; pa.Kpad[1] = 96;  pa.off[1] = 24576;
        pa.W[2] = W2r; pa.K[2] = 256; pa.M[2] = 512; pa.Kpad[2] = 256; pa.off[2] = 49152;
        pa.W[3] = W2o; pa.K[3] = 256; pa.M[3] = 512; pa.Kpad[3] = 256; pa.off[3] = 180224;
        pa.W[4] = W3r; pa.K[4] = 512; pa.M[4] = 512; pa.Kpad[4] = 512; pa.off[4] = 311296;
        pa.W[5] = W3o; pa.K[5] = 512; pa.M[5] = 512; pa.Kpad[5] = 512; pa.off[5] = 573440;
        pa.W[6] = Wfc; pa.K[6] = 512; pa.M[6] = 128; pa.Kpad[6] = 512; pa.off[6] = 835584;
        dim3 grid((512 * 512 + 255) / 256, 7);
        prep_all<<<grid, 256>>>(pa, wth, wtl);
    }
    prep_x<<<(N_NODES * 96 + 255) / 256, 256>>>(x, bAh, bAl);

    // ---- CSR build ----
    {
        int* pcnt; cudaGetSymbolAddress((void**)&pcnt, g_cnt);
        zero_int<<<(N_NODES + 255) / 256, 256>>>(pcnt, N_NODES);
    }
    hist_kernel<<<(N_EDGES + 255) / 256, 256>>>(ei);
    scan1<<<(N_NODES + 1023) / 1024, 1024>>>();
    scan2<<<1, 32>>>((N_NODES + 1023) / 1024);
    scan3<<<(N_NODES + 255) / 256, 256>>>();
    fill_kernel<<<(N_EDGES + 255) / 256, 256>>>(ei);

    // ---- Layer 1: 78 -> 256 ----
    gather78<<<gatherBlocks, 256>>>(x, aggh, aggl);
    {
        dim3 grid(2, gridY);
        dual_gemm_bf16<<<grid, 256, 81920>>>(aggh, aggl, bAh, bAl,
                                             wth + 0, wtl + 0,
                                             wth + 24576, wtl + 24576,
                                             b1, h1, bBh, bBl,
                                             N_NODES, 96, 256, 1);
    }

    // ---- Layer 2: 256 -> 512 ----
    gather_vec4<<<gatherBlocks, 256>>>(h1, 256, aggh, aggl);
    {
        dim3 grid(4, gridY);
        dual_gemm_bf16<<<grid, 256, 81920>>>(aggh, aggl, bBh, bBl,
                                             wth + 49152, wtl + 49152,
                                             wth + 180224, wtl + 180224,
                                             b2, h2, bAh, bAl,
                                             N_NODES, 256, 512, 1);
    }

    // ---- Layer 3: 512 -> 512 (no fp32 out; bf16 hi/lo feeds FC) ----
    gather_vec4<<<gatherBlocks, 256>>>(h2, 512, aggh, aggl);
    {
        dim3 grid(4, gridY);
        dual_gemm_bf16<<<grid, 256, 81920>>>(aggh, aggl, bAh, bAl,
                                             wth + 311296, wtl + 311296,
                                             wth + 573440, wtl + 573440,
                                             b3, (float*)nullptr, bBh, bBl,
                                             N_NODES, 512, 512, 1);
    }

    // ---- FC 512->128 via GEMM (no relu), then LN + ReLU + pool ----
    {
        dim3 grid(1, gridY);
        dual_gemm_bf16<<<grid, 256, 81920>>>(bBh, bBl,
                                             (__nv_bfloat16*)nullptr,
                                             (__nv_bfloat16*)nullptr,
                                             wth + 835584, wtl + 835584,
                                             (__nv_bfloat16*)nullptr,
                                             (__nv_bfloat16*)nullptr,
                                             bfc, h1,
                                             (__nv_bfloat16*)nullptr,
                                             (__nv_bfloat16*)nullptr,
                                             N_NODES, 512, 128, 0);
    }
    zero_kernel<<<128, 256>>>((float4*)pooled, N_GRAPHS * 128 / 4);
    ln_pool<<<(N_NODES + LN_ROWS - 1) / LN_ROWS, 128>>>(
        h1, lng, lnb, batch, x_atom, pooled, N_NODES);
}

// round 11
// speedup vs baseline: 1.6901x; 1.1309x over previous
#include <cuda_runtime.h>
#include <cuda_bf16.h>
#include <cstdint>

#define N_NODES 50000
#define N_EDGES 800000
#define N_GRAPHS 1024
#define NBLK 391                 // ceil(50000/128)
#define TILE_E 5120              // elems per 10240B tile (128 rows x 40)
#define FEAT_E ((size_t)NBLK * 16 * TILE_E)

// ---------------- device-global scratch (allocation-free rule) -------------
__device__ float g_h1[(size_t)N_NODES * 256];   // fp32 layer1 out (gather src) / FC z
__device__ float g_h2[(size_t)N_NODES * 512];
// tiled bf16 feature buffers: [block][chunk][128x40]
__device__ __nv_bfloat16 g_agg_hi[FEAT_E];
__device__ __nv_bfloat16 g_agg_lo[FEAT_E];
__device__ __nv_bfloat16 g_bufA_hi[FEAT_E];
__device__ __nv_bfloat16 g_bufA_lo[FEAT_E];
__device__ __nv_bfloat16 g_bufB_hi[FEAT_E];
__device__ __nv_bfloat16 g_bufB_lo[FEAT_E];
// tiled weights (bf16 hi/lo), offsets in elems:
// W1r:0 W1o:30720 W2r:61440 W2o:225280 W3r:389120 W3o:716800 Wfc:1044480
__device__ __nv_bfloat16 g_wt_hi[1126400];
__device__ __nv_bfloat16 g_wt_lo[1126400];
// CSR
__device__ int g_cnt[N_NODES];
__device__ int g_off[N_NODES + 1];
__device__ int g_cur[N_NODES];
__device__ int g_srcs[N_EDGES];
__device__ int g_bsum[64];

// ---------------------------------------------------------------------------
__global__ void zero_kernel(float4* __restrict__ p, int n4) {
    int i = blockIdx.x * blockDim.x + threadIdx.x;
    int stride = gridDim.x * blockDim.x;
    float4 z = make_float4(0.f, 0.f, 0.f, 0.f);
    for (; i < n4; i += stride) p[i] = z;
}

__global__ void zero_int(int* __restrict__ p, int n) {
    int i = blockIdx.x * blockDim.x + threadIdx.x;
    if (i < n) p[i] = 0;
}

// ---------------------------------------------------------------------------
// Fused weight prep -> tiled [colblock][chunk][128x40] bf16 hi/lo
// ---------------------------------------------------------------------------
struct PrepArgs {
    const float* W[7];
    int K[7];
    int M[7];
    int Kpad[7];
    int off[7];
};

__global__ void prep_all(PrepArgs a,
                         __nv_bfloat16* __restrict__ hi,
                         __nv_bfloat16* __restrict__ lo) {
    int seg = blockIdx.y;
    int idx = blockIdx.x * blockDim.x + threadIdx.x;
    int Kpad = a.Kpad[seg];
    if (idx >= a.M[seg] * Kpad) return;
    int n = idx / Kpad, k = idx % Kpad;
    int K = a.K[seg];
    int nch = Kpad >> 5;
    float v = (k < K) ? a.W[seg][(size_t)k * a.M[seg] + n] : 0.f;
    __nv_bfloat16 h = __float2bfloat16(v);
    size_t o = (size_t)a.off[seg]
             + ((size_t)(n >> 7) * nch + (k >> 5)) * TILE_E
             + (n & 127) * 40 + (k & 31);
    hi[o] = h;
    lo[o] = __float2bfloat16(v - __bfloat162float(h));
}

// x [N,78] fp32 -> tiled hi/lo (Kpad 96, nch 3)
__global__ void prep_x(const float* __restrict__ x,
                       __nv_bfloat16* __restrict__ hi,
                       __nv_bfloat16* __restrict__ lo) {
    int idx = blockIdx.x * blockDim.x + threadIdx.x;
    if (idx >= N_NODES * 96) return;
    int n = idx / 96, k = idx % 96;
    float v = (k < 78) ? x[(size_t)n * 78 + k] : 0.f;
    __nv_bfloat16 h = __float2bfloat16(v);
    size_t o = ((size_t)(n >> 7) * 3 + (k >> 5)) * TILE_E
             + (n & 127) * 40 + (k & 31);
    hi[o] = h;
    lo[o] = __float2bfloat16(v - __bfloat162float(h));
}

// ---------------------------------------------------------------------------
// CSR build
// ---------------------------------------------------------------------------
__global__ void hist_kernel(const int* __restrict__ ei) {
    int e = blockIdx.x * blockDim.x + threadIdx.x;
    if (e < N_EDGES) atomicAdd(&g_cnt[ei[N_EDGES + e]], 1);
}

__global__ void scan1(void) {
    __shared__ int sm[1024];
    int tid = threadIdx.x;
    int i = blockIdx.x * 1024 + tid;
    int v = (i < N_NODES) ? g_cnt[i] : 0;
    sm[tid] = v;
    __syncthreads();
    for (int o = 1; o < 1024; o <<= 1) {
        int t = (tid >= o) ? sm[tid - o] : 0;
        __syncthreads();
        sm[tid] += t;
        __syncthreads();
    }
    if (i < N_NODES) g_off[i] = sm[tid] - v;
    if (tid == 1023) g_bsum[blockIdx.x] = sm[1023];
}

__global__ void scan2(int nblk) {
    if (threadIdx.x == 0) {
        int run = 0;
        for (int b = 0; b < nblk; ++b) {
            int t = g_bsum[b];
            g_bsum[b] = run;
            run += t;
        }
    }
}

__global__ void scan3(void) {
    int i = blockIdx.x * blockDim.x + threadIdx.x;
    if (i < N_NODES) {
        int o = g_off[i] + g_bsum[i >> 10];
        g_off[i] = o;
        g_cur[i] = o;
    }
    if (i == 0) g_off[N_NODES] = N_EDGES;
}

__global__ void fill_kernel(const int* __restrict__ ei) {
    int e = blockIdx.x * blockDim.x + threadIdx.x;
    if (e >= N_EDGES) return;
    int s = ei[e], t = ei[N_EDGES + e];
    int pos = atomicAdd(&g_cur[t], 1);
    g_srcs[pos] = s;
}

// ---------------------------------------------------------------------------
// CSR gather -> tiled bf16 hi/lo.  Warp per node.  Single fp32 LDG stream.
// ---------------------------------------------------------------------------
__global__ void gather78(const float* __restrict__ x,
                         __nv_bfloat16* __restrict__ ahi,
                         __nv_bfloat16* __restrict__ alo) {
    int n = (blockIdx.x * blockDim.x + threadIdx.x) >> 5;
    int lane = threadIdx.x & 31;
    if (n >= N_NODES) return;
    int jb = g_off[n], je = g_off[n + 1];
    float a0 = 0.f, a1 = 0.f, a2 = 0.f;
    for (int j = jb; j < je; ++j) {
        const float* xr = x + (size_t)g_srcs[j] * 78;
        a0 += __ldg(xr + lane);
        a1 += __ldg(xr + lane + 32);
        if (lane < 14) a2 += __ldg(xr + lane + 64);
    }
    float vals[3] = {a0, a1, (lane < 14) ? a2 : 0.f};
    size_t tbase = (size_t)(n >> 7) * 3;
    int rr = (n & 127) * 40 + lane;
    #pragma unroll
    for (int i = 0; i < 3; ++i) {
        size_t o = (tbase + i) * TILE_E + rr;
        __nv_bfloat16 h = __float2bfloat16(vals[i]);
        ahi[o] = h;
        alo[o] = __float2bfloat16(vals[i] - __bfloat162float(h));
    }
}

__global__ void gather_vec4(const float* __restrict__ x, int d,
                            __nv_bfloat16* __restrict__ ahi,
                            __nv_bfloat16* __restrict__ alo) {
    int n = (blockIdx.x * blockDim.x + threadIdx.x) >> 5;
    int lane = threadIdx.x & 31;
    if (n >= N_NODES) return;
    int jb = g_off[n], je = g_off[n + 1];
    int ni = d >> 7;
    int nch = d >> 5;
    float4 acc[4];
    #pragma unroll
    for (int i = 0; i < 4; ++i) acc[i] = make_float4(0.f, 0.f, 0.f, 0.f);
    for (int j = jb; j < je; ++j) {
        const float4* xr = (const float4*)(x + (size_t)g_srcs[j] * d);
        #pragma unroll 4
        for (int i = 0; i < ni; ++i) {
            float4 v = __ldg(xr + lane + i * 32);
            acc[i].x += v.x; acc[i].y += v.y; acc[i].z += v.z; acc[i].w += v.w;
        }
    }
    size_t tb = (size_t)(n >> 7) * nch;
    int rbase = (n & 127) * 40 + (lane & 7) * 4;
    for (int i = 0; i < ni; ++i) {
        int ch = (lane >> 3) + 4 * i;
        float4 a = acc[i];
        __nv_bfloat162 h01 = __floats2bfloat162_rn(a.x, a.y);
        __nv_bfloat162 h23 = __floats2bfloat162_rn(a.z, a.w);
        __nv_bfloat162 l01 = __floats2bfloat162_rn(a.x - __bfloat162float(h01.x),
                                                   a.y - __bfloat162float(h01.y));
        __nv_bfloat162 l23 = __floats2bfloat162_rn(a.z - __bfloat162float(h23.x),
                                                   a.w - __bfloat162float(h23.y));
        size_t o = (tb + ch) * TILE_E + rbase;
        *(uint2*)(ahi + o) = make_uint2(*(unsigned*)&h01, *(unsigned*)&h23);
        *(uint2*)(alo + o) = make_uint2(*(unsigned*)&l01, *(unsigned*)&l23);
    }
}

// ---------------------------------------------------------------------------
// mma / ldmatrix / bulk-copy helpers
// ---------------------------------------------------------------------------
__device__ __forceinline__ void mma_bf16(float* c, const unsigned* a,
                                         unsigned b0, unsigned b1) {
    asm volatile(
        "mma.sync.aligned.m16n8k16.row.col.f32.bf16.bf16.f32 "
        "{%0,%1,%2,%3}, {%4,%5,%6,%7}, {%8,%9}, {%0,%1,%2,%3};"
        : "+f"(c[0]), "+f"(c[1]), "+f"(c[2]), "+f"(c[3])
        : "r"(a[0]), "r"(a[1]), "r"(a[2]), "r"(a[3]), "r"(b0), "r"(b1));
}

__device__ __forceinline__ void ldm_x4(unsigned* r, uint32_t addr) {
    asm volatile(
        "ldmatrix.sync.aligned.m8n8.x4.shared.b16 {%0,%1,%2,%3}, [%4];"
        : "=r"(r[0]), "=r"(r[1]), "=r"(r[2]), "=r"(r[3]) : "r"(addr));
}

__device__ __forceinline__ void ldm_x2(unsigned* r, uint32_t addr) {
    asm volatile(
        "ldmatrix.sync.aligned.m8n8.x2.shared.b16 {%0,%1}, [%2];"
        : "=r"(r[0]), "=r"(r[1]) : "r"(addr));
}

__device__ __forceinline__ void bulkcp(uint32_t dst, const void* src,
                                       uint32_t mbar) {
    asm volatile(
        "cp.async.bulk.shared::cluster.global.mbarrier::complete_tx::bytes "
        "[%0], [%1], %2, [%3];"
        :: "r"(dst), "l"(src), "r"(10240u), "r"(mbar) : "memory");
}

__device__ __forceinline__ void mbar_wait(uint32_t addr, uint32_t phase) {
    asm volatile(
        "{\n\t.reg .pred p;\n\t"
        "WL%=:\n\t"
        "mbarrier.try_wait.parity.acquire.cta.shared::cta.b64 p, [%0], %1, 0x989680;\n\t"
        "@p bra WD%=;\n\t"
        "bra WL%=;\n\t"
        "WD%=:\n\t}"
        :: "r"(addr), "r"(phase) : "memory");
}

// ---------------------------------------------------------------------------
// Dual/single GEMM (bf16 hi/lo 3-term split), cp.async.bulk double-buffered.
//   C = act(A1 @ B1 [+ A2 @ B2] + bias)
// All operands TILED: [block][chunk][128 rows x 40 elems] (10240B tiles).
// Loader: ONE elected thread, 4 bulk copies/iter (kills LDGSTS-issue bound).
// Compute identical to proven x2-fragment mainloop.
// ---------------------------------------------------------------------------
#define TILE_B 10240
#define STAGE_B 40960

__global__ __launch_bounds__(256, 2)
void dual_gemm_bf16(const __nv_bfloat16* __restrict__ A1h,
                    const __nv_bfloat16* __restrict__ A1l,
                    const __nv_bfloat16* __restrict__ A2h,
                    const __nv_bfloat16* __restrict__ A2l,
                    const __nv_bfloat16* __restrict__ B1h,
                    const __nv_bfloat16* __restrict__ B1l,
                    const __nv_bfloat16* __restrict__ B2h,
                    const __nv_bfloat16* __restrict__ B2l,
                    const float* __restrict__ bias, float* __restrict__ C,
                    __nv_bfloat16* __restrict__ Chi,
                    __nv_bfloat16* __restrict__ Clo,
                    int N, int Kpad, int M, int do_relu) {
    extern __shared__ __align__(16) char dynsmem[];
    __shared__ __align__(8) uint64_t s_mbar[2];
    uint32_t ubase = (uint32_t)__cvta_generic_to_shared(dynsmem);
    uint32_t mbase = (uint32_t)__cvta_generic_to_shared(s_mbar);

    int tid = threadIdx.x;
    int lane = tid & 31, wid = tid >> 5;
    int wr = wid & 3, wc = wid >> 2;
    int m0w = wr * 32, n0w = wc * 64;
    int gid = lane >> 2, tig = lane & 3;

    int rowBase = blockIdx.y * 128;
    int colBase = blockIdx.x * 128;

    int a_row = (lane & 7) + ((lane >> 3) & 1) * 8;
    int a_koff = (lane >> 4) * 16;
    int b_row = lane & 7;
    int b_koff = ((lane >> 3) & 1) * 16;

    if (tid == 0) {
        asm volatile("mbarrier.init.shared.b64 [%0], 1;" :: "r"(mbase) : "memory");
        asm volatile("mbarrier.init.shared.b64 [%0], 1;" :: "r"(mbase + 8) : "memory");
    }
    __syncthreads();

    float acc[2][8][4];
    #pragma unroll
    for (int mt = 0; mt < 2; mt++)
        #pragma unroll
        for (int nt = 0; nt < 8; nt++)
            #pragma unroll
            for (int i = 0; i < 4; i++) acc[mt][nt][i] = 0.f;

    const int nch = Kpad >> 5;
    const int npass = (A2h != nullptr) ? 2 : 1;
    const int T = npass * nch;

    auto issue = [&](int it, int st) {
        if (tid == 0) {
            int pass = (it >= nch) ? 1 : 0;
            int ch = it - pass * nch;
            const __nv_bfloat16* AH = pass ? A2h : A1h;
            const __nv_bfloat16* AL = pass ? A2l : A1l;
            const __nv_bfloat16* BH = pass ? B2h : B1h;
            const __nv_bfloat16* BL = pass ? B2l : B1l;
            uint32_t mb = mbase + st * 8;
            asm volatile("mbarrier.arrive.expect_tx.shared.b64 _, [%0], %1;"
                         :: "r"(mb), "r"(40960u) : "memory");
            uint32_t sb = ubase + st * STAGE_B;
            size_t at = ((size_t)blockIdx.y * nch + ch) * TILE_E;
            size_t bt = ((size_t)blockIdx.x * nch + ch) * TILE_E;
            bulkcp(sb,              AH + at, mb);
            bulkcp(sb + TILE_B,     AL + at, mb);
            bulkcp(sb + 2 * TILE_B, BH + bt, mb);
            bulkcp(sb + 3 * TILE_B, BL + bt, mb);
        }
    };

    int ph0 = 0, ph1 = 0;
    issue(0, 0);

    #pragma unroll 1
    for (int it = 0; it < T; ++it) {
        if (it + 1 < T) issue(it + 1, (it + 1) & 1);
        int st = it & 1;
        mbar_wait(mbase + st * 8, st ? ph1 : ph0);
        if (st) ph1 ^= 1; else ph0 ^= 1;

        uint32_t sb = ubase + st * STAGE_B;
        uint32_t uAh = sb, uAl = sb + TILE_B;
        uint32_t uBh = sb + 2 * TILE_B, uBl = sb + 3 * TILE_B;

        #pragma unroll
        for (int ks = 0; ks < 2; ++ks) {
            int kb = ks * 32;
            unsigned ah[2][4], al[2][4];
            #pragma unroll
            for (int mt = 0; mt < 2; mt++) {
                uint32_t ao = (uint32_t)((m0w + mt * 16 + a_row) * 80
                                         + kb + a_koff);
                ldm_x4(ah[mt], uAh + ao);
                ldm_x4(al[mt], uAl + ao);
            }
            #pragma unroll
            for (int nt = 0; nt < 8; nt++) {
                uint32_t bo = (uint32_t)((n0w + nt * 8 + b_row) * 80
                                         + kb + b_koff);
                unsigned bh[2], bl[2];
                ldm_x2(bh, uBh + bo);
                ldm_x2(bl, uBl + bo);
                #pragma unroll
                for (int mt = 0; mt < 2; mt++) {
                    mma_bf16(acc[mt][nt], ah[mt], bh[0], bh[1]);
                    mma_bf16(acc[mt][nt], al[mt], bh[0], bh[1]);
                    mma_bf16(acc[mt][nt], ah[mt], bl[0], bl[1]);
                }
            }
        }
        __syncthreads();   // all reads done before next bulk overwrites stage
    }

    // ---- Epilogue ----
    const int nchC = M >> 5;
    #pragma unroll
    for (int mt = 0; mt < 2; mt++) {
        #pragma unroll
        for (int nt = 0; nt < 8; nt++) {
            int r = rowBase + m0w + mt * 16 + gid;
            int c = colBase + n0w + nt * 8 + tig * 2;
            float b0v = bias[c], b1v = bias[c + 1];
            #pragma unroll
            for (int half = 0; half < 2; ++half) {
                int rr = r + half * 8;
                if (rr >= N) continue;
                float v0 = acc[mt][nt][2 * half + 0] + b0v;
                float v1 = acc[mt][nt][2 * half + 1] + b1v;
                if (do_relu) {
                    v0 = v0 > 0.f ? v0 : 0.f;
                    v1 = v1 > 0.f ? v1 : 0.f;
                }
                if (C) {
                    size_t o = (size_t)rr * M + c;
                    C[o] = v0;
                    C[o + 1] = v1;
                }
                if (Chi) {
                    size_t o = ((size_t)blockIdx.y * nchC + (c >> 5)) * TILE_E
                             + (rr & 127) * 40 + (c & 31);
                    __nv_bfloat162 hh = __floats2bfloat162_rn(v0, v1);
                    __nv_bfloat162 ll = __floats2bfloat162_rn(
                        v0 - __bfloat162float(hh.x), v1 - __bfloat162float(hh.y));
                    *(unsigned*)(Chi + o) = *(unsigned*)&hh;
                    *(unsigned*)(Clo + o) = *(unsigned*)&ll;
                }
            }
        }
    }
}

// ---------------------------------------------------------------------------
// LayerNorm(128) + ReLU + pooling.  Warp per row group; no block syncs.
// ---------------------------------------------------------------------------
#define LNW 32

__global__ __launch_bounds__(256)
void ln_pool(const float* __restrict__ z, const float* __restrict__ lng,
             const float* __restrict__ lnb, const int* __restrict__ batch,
             float* __restrict__ xa, float* __restrict__ pooled, int N) {
    int warp = (blockIdx.x * blockDim.x + threadIdx.x) >> 5;
    int lane = threadIdx.x & 31;
    int r0 = warp * LNW;
    if (r0 >= N) return;
    int r1 = min(r0 + LNW, N);

    float4 g = ((const float4*)lng)[lane];
    float4 b = ((const float4*)lnb)[lane];

    float4 pacc = make_float4(0.f, 0.f, 0.f, 0.f);
    int curg = -1;
    for (int r = r0; r < r1; ++r) {
        float4 v = ((const float4*)(z + (size_t)r * 128))[lane];
        float s = v.x + v.y + v.z + v.w;
        float s2 = v.x * v.x + v.y * v.y + v.z * v.z + v.w * v.w;
        #pragma unroll
        for (int o = 16; o > 0; o >>= 1) {
            s  += __shfl_xor_sync(0xffffffffu, s, o);
            s2 += __shfl_xor_sync(0xffffffffu, s2, o);
        }
        float mu = s * (1.f / 128.f);
        float var = s2 * (1.f / 128.f) - mu * mu;
        float inv = rsqrtf(var + 1e-5f);
        float4 zz;
        zz.x = fmaxf((v.x - mu) * inv * g.x + b.x, 0.f);
        zz.y = fmaxf((v.y - mu) * inv * g.y + b.y, 0.f);
        zz.z = fmaxf((v.z - mu) * inv * g.z + b.z, 0.f);
        zz.w = fmaxf((v.w - mu) * inv * g.w + b.w, 0.f);
        ((float4*)(xa + (size_t)r * 128))[lane] = zz;

        int gb = batch[r];
        if (gb != curg) {
            if (curg >= 0) {
                float* pd = pooled + (size_t)curg * 128 + lane * 4;
                atomicAdd(pd + 0, pacc.x);
                atomicAdd(pd + 1, pacc.y);
                atomicAdd(pd + 2, pacc.z);
                atomicAdd(pd + 3, pacc.w);
            }
            curg = gb;
            pacc = make_float4(0.f, 0.f, 0.f, 0.f);
        }
        pacc.x += zz.x; pacc.y += zz.y; pacc.z += zz.z; pacc.w += zz.w;
    }
    if (curg >= 0) {
        float* pd = pooled + (size_t)curg * 128 + lane * 4;
        atomicAdd(pd + 0, pacc.x);
        atomicAdd(pd + 1, pacc.y);
        atomicAdd(pd + 2, pacc.z);
        atomicAdd(pd + 3, pacc.w);
    }
}

// ---------------------------------------------------------------------------
// Launch
// ---------------------------------------------------------------------------
extern "C" void kernel_launch(void* const* d_in, const int* in_sizes, int n_in,
                              void* d_out, int out_size) {
    const float* x     = (const float*)d_in[0];
    const int*   ei    = (const int*)d_in[1];
    const int*   batch = (const int*)d_in[2];
    const float* W1r = (const float*)d_in[3];
    const float* b1  = (const float*)d_in[4];
    const float* W1o = (const float*)d_in[5];
    const float* W2r = (const float*)d_in[6];
    const float* b2  = (const float*)d_in[7];
    const float* W2o = (const float*)d_in[8];
    const float* W3r = (const float*)d_in[9];
    const float* b3  = (const float*)d_in[10];
    const float* W3o = (const float*)d_in[11];
    const float* Wfc = (const float*)d_in[12];
    const float* bfc = (const float*)d_in[13];
    const float* lng = (const float*)d_in[14];
    const float* lnb = (const float*)d_in[15];

    float* out = (float*)d_out;
    float* x_atom = out;
    float* pooled = out + (size_t)N_NODES * 128;

    float *h1, *h2;
    __nv_bfloat16 *aggh, *aggl, *bAh, *bAl, *bBh, *bBl, *wth, *wtl;
    cudaGetSymbolAddress((void**)&h1, g_h1);
    cudaGetSymbolAddress((void**)&h2, g_h2);
    cudaGetSymbolAddress((void**)&aggh, g_agg_hi);
    cudaGetSymbolAddress((void**)&aggl, g_agg_lo);
    cudaGetSymbolAddress((void**)&bAh, g_bufA_hi);
    cudaGetSymbolAddress((void**)&bAl, g_bufA_lo);
    cudaGetSymbolAddress((void**)&bBh, g_bufB_hi);
    cudaGetSymbolAddress((void**)&bBl, g_bufB_lo);
    cudaGetSymbolAddress((void**)&wth, g_wt_hi);
    cudaGetSymbolAddress((void**)&wtl, g_wt_lo);

    cudaFuncSetAttribute(dual_gemm_bf16,
                         cudaFuncAttributeMaxDynamicSharedMemorySize, 81920);

    const int gridY = NBLK;
    const int gatherBlocks = (N_NODES * 32 + 255) / 256;

    // ---- Weight prep (single fused launch, tiled layout) ----
    {
        PrepArgs pa;
        pa.W[0] = W1r; pa.K[0] = 78;  pa.M[0] = 256; pa.Kpad[0] = 96;  pa.off[0] = 0;
        pa.W[1] = W1o; pa.K[1] = 78;  pa.M[1] = 256; pa.Kpad[1] = 96;  pa.off[1] = 30720;
        pa.W[2] = W2r; pa.K[2] = 256; pa.M[2] = 512; pa.Kpad[2] = 256; pa.off[2] = 61440;
        pa.W[3] = W2o; pa.K[3] = 256; pa.M[3] = 512; pa.Kpad[3] = 256; pa.off[3] = 225280;
        pa.W[4] = W3r; pa.K[4] = 512; pa.M[4] = 512; pa.Kpad[4] = 512; pa.off[4] = 389120;
        pa.W[5] = W3o; pa.K[5] = 512; pa.M[5] = 512; pa.Kpad[5] = 512; pa.off[5] = 716800;
        pa.W[6] = Wfc; pa.K[6] = 512; pa.M[6] = 128; pa.Kpad[6] = 512; pa.off[6] = 1044480;
        dim3 grid((512 * 512 + 255) / 256, 7);
        prep_all<<<grid, 256>>>(pa, wth, wtl);
    }
    prep_x<<<(N_NODES * 96 + 255) / 256, 256>>>(x, bAh, bAl);

    // ---- CSR build ----
    {
        int* pcnt; cudaGetSymbolAddress((void**)&pcnt, g_cnt);
        zero_int<<<(N_NODES + 255) / 256, 256>>>(pcnt, N_NODES);
    }
    hist_kernel<<<(N_EDGES + 255) / 256, 256>>>(ei);
    scan1<<<(N_NODES + 1023) / 1024, 1024>>>();
    scan2<<<1, 32>>>((N_NODES + 1023) / 1024);
    scan3<<<(N_NODES + 255) / 256, 256>>>();
    fill_kernel<<<(N_EDGES + 255) / 256, 256>>>(ei);

    // ---- Layer 1: 78 -> 256 ----
    gather78<<<gatherBlocks, 256>>>(x, aggh, aggl);
    {
        dim3 grid(2, gridY);
        dual_gemm_bf16<<<grid, 256, 81920>>>(aggh, aggl, bAh, bAl,
                                             wth + 0, wtl + 0,
                                             wth + 30720, wtl + 30720,
                                             b1, h1, bBh, bBl,
                                             N_NODES, 96, 256, 1);
    }

    // ---- Layer 2: 256 -> 512 ----
    gather_vec4<<<gatherBlocks, 256>>>(h1, 256, aggh, aggl);
    {
        dim3 grid(4, gridY);
        dual_gemm_bf16<<<grid, 256, 81920>>>(aggh, aggl, bBh, bBl,
                                             wth + 61440, wtl + 61440,
                                             wth + 225280, wtl + 225280,
                                             b2, h2, bAh, bAl,
                                             N_NODES, 256, 512, 1);
    }

    // ---- Layer 3: 512 -> 512 ----
    gather_vec4<<<gatherBlocks, 256>>>(h2, 512, aggh, aggl);
    {
        dim3 grid(4, gridY);
        dual_gemm_bf16<<<grid, 256, 81920>>>(aggh, aggl, bAh, bAl,
                                             wth + 389120, wtl + 389120,
                                             wth + 716800, wtl + 716800,
                                             b3, (float*)nullptr, bBh, bBl,
                                             N_NODES, 512, 512, 1);
    }

    // ---- FC 512->128 via GEMM (no relu), then LN + ReLU + pool ----
    {
        dim3 grid(1, gridY);
        dual_gemm_bf16<<<grid, 256, 81920>>>(bBh, bBl,
                                             (__nv_bfloat16*)nullptr,
                                             (__nv_bfloat16*)nullptr,
                                             wth + 1044480, wtl + 1044480,
                                             (__nv_bfloat16*)nullptr,
                                             (__nv_bfloat16*)nullptr,
                                             bfc, h1,
                                             (__nv_bfloat16*)nullptr,
                                             (__nv_bfloat16*)nullptr,
                                             N_NODES, 512, 128, 0);
    }
    zero_kernel<<<128, 256>>>((float4*)pooled, N_GRAPHS * 128 / 4);
    {
        int warps = (N_NODES + LNW - 1) / LNW;
        ln_pool<<<(warps * 32 + 255) / 256, 256>>>(
            h1, lng, lnb, batch, x_atom, pooled, N_NODES);
    }
}

// round 12
// speedup vs baseline: 1.6943x; 1.0025x over previous
#include <cuda_runtime.h>
#include <cuda_bf16.h>
#include <cstdint>

#define N_NODES 50000
#define N_EDGES 800000
#define N_GRAPHS 1024
#define NBLK 391                 // ceil(50000/128)
#define TILE_E 5120              // elems per 10240B tile (128 rows x 40)
#define FEAT_E ((size_t)NBLK * 16 * TILE_E)

// ---------------- device-global scratch (allocation-free rule) -------------
__device__ float g_h1[(size_t)N_NODES * 256];   // fp32 layer1 out (gather src) / FC z
__device__ float g_h2[(size_t)N_NODES * 512];
// tiled bf16 feature buffers: [block][chunk][128x40]
__device__ __nv_bfloat16 g_agg_hi[FEAT_E];
__device__ __nv_bfloat16 g_agg_lo[FEAT_E];
__device__ __nv_bfloat16 g_bufA_hi[FEAT_E];
__device__ __nv_bfloat16 g_bufA_lo[FEAT_E];
__device__ __nv_bfloat16 g_bufB_hi[FEAT_E];
__device__ __nv_bfloat16 g_bufB_lo[FEAT_E];
// tiled weights (bf16 hi/lo), offsets in elems:
// W1r:0 W1o:30720 W2r:61440 W2o:225280 W3r:389120 W3o:716800 Wfc:1044480
__device__ __nv_bfloat16 g_wt_hi[1126400];
__device__ __nv_bfloat16 g_wt_lo[1126400];
// CSR
__device__ int g_cnt[N_NODES];
__device__ int g_off[N_NODES + 1];
__device__ int g_cur[N_NODES];
__device__ int g_srcs[N_EDGES];
__device__ int g_bsum[64];

// ---------------------------------------------------------------------------
__global__ void zero_kernel(float4* __restrict__ p, int n4) {
    int i = blockIdx.x * blockDim.x + threadIdx.x;
    int stride = gridDim.x * blockDim.x;
    float4 z = make_float4(0.f, 0.f, 0.f, 0.f);
    for (; i < n4; i += stride) p[i] = z;
}

__global__ void zero_int(int* __restrict__ p, int n) {
    int i = blockIdx.x * blockDim.x + threadIdx.x;
    if (i < n) p[i] = 0;
}

// ---------------------------------------------------------------------------
// Fused weight prep -> tiled [colblock][chunk][128x40] bf16 hi/lo
// ---------------------------------------------------------------------------
struct PrepArgs {
    const float* W[7];
    int K[7];
    int M[7];
    int Kpad[7];
    int off[7];
};

__global__ void prep_all(PrepArgs a,
                         __nv_bfloat16* __restrict__ hi,
                         __nv_bfloat16* __restrict__ lo) {
    int seg = blockIdx.y;
    int idx = blockIdx.x * blockDim.x + threadIdx.x;
    int Kpad = a.Kpad[seg];
    if (idx >= a.M[seg] * Kpad) return;
    int n = idx / Kpad, k = idx % Kpad;
    int K = a.K[seg];
    int nch = Kpad >> 5;
    float v = (k < K) ? a.W[seg][(size_t)k * a.M[seg] + n] : 0.f;
    __nv_bfloat16 h = __float2bfloat16(v);
    size_t o = (size_t)a.off[seg]
             + ((size_t)(n >> 7) * nch + (k >> 5)) * TILE_E
             + (n & 127) * 40 + (k & 31);
    hi[o] = h;
    lo[o] = __float2bfloat16(v - __bfloat162float(h));
}

// x [N,78] fp32 -> tiled hi/lo (Kpad 96, nch 3)
__global__ void prep_x(const float* __restrict__ x,
                       __nv_bfloat16* __restrict__ hi,
                       __nv_bfloat16* __restrict__ lo) {
    int idx = blockIdx.x * blockDim.x + threadIdx.x;
    if (idx >= N_NODES * 96) return;
    int n = idx / 96, k = idx % 96;
    float v = (k < 78) ? x[(size_t)n * 78 + k] : 0.f;
    __nv_bfloat16 h = __float2bfloat16(v);
    size_t o = ((size_t)(n >> 7) * 3 + (k >> 5)) * TILE_E
             + (n & 127) * 40 + (k & 31);
    hi[o] = h;
    lo[o] = __float2bfloat16(v - __bfloat162float(h));
}

// ---------------------------------------------------------------------------
// CSR build
// ---------------------------------------------------------------------------
__global__ void hist_kernel(const int* __restrict__ ei) {
    int e = blockIdx.x * blockDim.x + threadIdx.x;
    if (e < N_EDGES) atomicAdd(&g_cnt[ei[N_EDGES + e]], 1);
}

__global__ void scan1(void) {
    __shared__ int sm[1024];
    int tid = threadIdx.x;
    int i = blockIdx.x * 1024 + tid;
    int v = (i < N_NODES) ? g_cnt[i] : 0;
    sm[tid] = v;
    __syncthreads();
    for (int o = 1; o < 1024; o <<= 1) {
        int t = (tid >= o) ? sm[tid - o] : 0;
        __syncthreads();
        sm[tid] += t;
        __syncthreads();
    }
    if (i < N_NODES) g_off[i] = sm[tid] - v;
    if (tid == 1023) g_bsum[blockIdx.x] = sm[1023];
}

// scan3 folds the block-sum prefix (previously scan2) into each thread.
__global__ void scan3(void) {
    int i = blockIdx.x * blockDim.x + threadIdx.x;
    if (i < N_NODES) {
        int blk = i >> 10;
        int run = 0;
        for (int b = 0; b < blk; ++b) run += g_bsum[b];
        int o = g_off[i] + run;
        g_off[i] = o;
        g_cur[i] = o;
    }
    if (i == 0) g_off[N_NODES] = N_EDGES;
}

__global__ void fill_kernel(const int* __restrict__ ei) {
    int e = blockIdx.x * blockDim.x + threadIdx.x;
    if (e >= N_EDGES) return;
    int s = ei[e], t = ei[N_EDGES + e];
    int pos = atomicAdd(&g_cur[t], 1);
    g_srcs[pos] = s;
}

// ---------------------------------------------------------------------------
// CSR gather -> tiled bf16 hi/lo.  Warp per node.  Single fp32 LDG stream.
// ---------------------------------------------------------------------------
__global__ void gather78(const float* __restrict__ x,
                         __nv_bfloat16* __restrict__ ahi,
                         __nv_bfloat16* __restrict__ alo) {
    int n = (blockIdx.x * blockDim.x + threadIdx.x) >> 5;
    int lane = threadIdx.x & 31;
    if (n >= N_NODES) return;
    int jb = g_off[n], je = g_off[n + 1];
    float a0 = 0.f, a1 = 0.f, a2 = 0.f;
    for (int j = jb; j < je; ++j) {
        const float* xr = x + (size_t)g_srcs[j] * 78;
        a0 += __ldg(xr + lane);
        a1 += __ldg(xr + lane + 32);
        if (lane < 14) a2 += __ldg(xr + lane + 64);
    }
    float vals[3] = {a0, a1, (lane < 14) ? a2 : 0.f};
    size_t tbase = (size_t)(n >> 7) * 3;
    int rr = (n & 127) * 40 + lane;
    #pragma unroll
    for (int i = 0; i < 3; ++i) {
        size_t o = (tbase + i) * TILE_E + rr;
        __nv_bfloat16 h = __float2bfloat16(vals[i]);
        ahi[o] = h;
        alo[o] = __float2bfloat16(vals[i] - __bfloat162float(h));
    }
}

__global__ void gather_vec4(const float* __restrict__ x, int d,
                            __nv_bfloat16* __restrict__ ahi,
                            __nv_bfloat16* __restrict__ alo) {
    int n = (blockIdx.x * blockDim.x + threadIdx.x) >> 5;
    int lane = threadIdx.x & 31;
    if (n >= N_NODES) return;
    int jb = g_off[n], je = g_off[n + 1];
    int ni = d >> 7;
    int nch = d >> 5;
    float4 acc[4];
    #pragma unroll
    for (int i = 0; i < 4; ++i) acc[i] = make_float4(0.f, 0.f, 0.f, 0.f);
    for (int j = jb; j < je; ++j) {
        const float4* xr = (const float4*)(x + (size_t)g_srcs[j] * d);
        #pragma unroll 4
        for (int i = 0; i < ni; ++i) {
            float4 v = __ldg(xr + lane + i * 32);
            acc[i].x += v.x; acc[i].y += v.y; acc[i].z += v.z; acc[i].w += v.w;
        }
    }
    size_t tb = (size_t)(n >> 7) * nch;
    int rbase = (n & 127) * 40 + (lane & 7) * 4;
    for (int i = 0; i < ni; ++i) {
        int ch = (lane >> 3) + 4 * i;
        float4 a = acc[i];
        __nv_bfloat162 h01 = __floats2bfloat162_rn(a.x, a.y);
        __nv_bfloat162 h23 = __floats2bfloat162_rn(a.z, a.w);
        __nv_bfloat162 l01 = __floats2bfloat162_rn(a.x - __bfloat162float(h01.x),
                                                   a.y - __bfloat162float(h01.y));
        __nv_bfloat162 l23 = __floats2bfloat162_rn(a.z - __bfloat162float(h23.x),
                                                   a.w - __bfloat162float(h23.y));
        size_t o = (tb + ch) * TILE_E + rbase;
        *(uint2*)(ahi + o) = make_uint2(*(unsigned*)&h01, *(unsigned*)&h23);
        *(uint2*)(alo + o) = make_uint2(*(unsigned*)&l01, *(unsigned*)&l23);
    }
}

// ---------------------------------------------------------------------------
// mma / ldmatrix / bulk-copy helpers
// ---------------------------------------------------------------------------
__device__ __forceinline__ void mma_bf16(float* c, const unsigned* a,
                                         unsigned b0, unsigned b1) {
    asm volatile(
        "mma.sync.aligned.m16n8k16.row.col.f32.bf16.bf16.f32 "
        "{%0,%1,%2,%3}, {%4,%5,%6,%7}, {%8,%9}, {%0,%1,%2,%3};"
        : "+f"(c[0]), "+f"(c[1]), "+f"(c[2]), "+f"(c[3])
        : "r"(a[0]), "r"(a[1]), "r"(a[2]), "r"(a[3]), "r"(b0), "r"(b1));
}

__device__ __forceinline__ void ldm_x4(unsigned* r, uint32_t addr) {
    asm volatile(
        "ldmatrix.sync.aligned.m8n8.x4.shared.b16 {%0,%1,%2,%3}, [%4];"
        : "=r"(r[0]), "=r"(r[1]), "=r"(r[2]), "=r"(r[3]) : "r"(addr));
}

__device__ __forceinline__ void ldm_x2(unsigned* r, uint32_t addr) {
    asm volatile(
        "ldmatrix.sync.aligned.m8n8.x2.shared.b16 {%0,%1}, [%2];"
        : "=r"(r[0]), "=r"(r[1]) : "r"(addr));
}

__device__ __forceinline__ void bulkcp(uint32_t dst, const void* src,
                                       uint32_t mbar) {
    asm volatile(
        "cp.async.bulk.shared::cluster.global.mbarrier::complete_tx::bytes "
        "[%0], [%1], %2, [%3];"
        :: "r"(dst), "l"(src), "r"(10240u), "r"(mbar) : "memory");
}

__device__ __forceinline__ void mbar_wait(uint32_t addr, uint32_t phase) {
    asm volatile(
        "{\n\t.reg .pred p;\n\t"
        "WL%=:\n\t"
        "mbarrier.try_wait.parity.acquire.cta.shared::cta.b64 p, [%0], %1, 0x989680;\n\t"
        "@p bra WD%=;\n\t"
        "bra WL%=;\n\t"
        "WD%=:\n\t}"
        :: "r"(addr), "r"(phase) : "memory");
}

// ---------------------------------------------------------------------------
// Dual/single GEMM (bf16 hi/lo 3-term split), cp.async.bulk double-buffered.
// ---------------------------------------------------------------------------
#define TILE_B 10240
#define STAGE_B 40960

__global__ __launch_bounds__(256, 2)
void dual_gemm_bf16(const __nv_bfloat16* __restrict__ A1h,
                    const __nv_bfloat16* __restrict__ A1l,
                    const __nv_bfloat16* __restrict__ A2h,
                    const __nv_bfloat16* __restrict__ A2l,
                    const __nv_bfloat16* __restrict__ B1h,
                    const __nv_bfloat16* __restrict__ B1l,
                    const __nv_bfloat16* __restrict__ B2h,
                    const __nv_bfloat16* __restrict__ B2l,
                    const float* __restrict__ bias, float* __restrict__ C,
                    __nv_bfloat16* __restrict__ Chi,
                    __nv_bfloat16* __restrict__ Clo,
                    int N, int Kpad, int M, int do_relu) {
    extern __shared__ __align__(16) char dynsmem[];
    __shared__ __align__(8) uint64_t s_mbar[2];
    uint32_t ubase = (uint32_t)__cvta_generic_to_shared(dynsmem);
    uint32_t mbase = (uint32_t)__cvta_generic_to_shared(s_mbar);

    int tid = threadIdx.x;
    int lane = tid & 31, wid = tid >> 5;
    int wr = wid & 3, wc = wid >> 2;
    int m0w = wr * 32, n0w = wc * 64;
    int gid = lane >> 2, tig = lane & 3;

    int rowBase = blockIdx.y * 128;
    int colBase = blockIdx.x * 128;

    int a_row = (lane & 7) + ((lane >> 3) & 1) * 8;
    int a_koff = (lane >> 4) * 16;
    int b_row = lane & 7;
    int b_koff = ((lane >> 3) & 1) * 16;

    if (tid == 0) {
        asm volatile("mbarrier.init.shared.b64 [%0], 1;" :: "r"(mbase) : "memory");
        asm volatile("mbarrier.init.shared.b64 [%0], 1;" :: "r"(mbase + 8) : "memory");
    }
    __syncthreads();

    float acc[2][8][4];
    #pragma unroll
    for (int mt = 0; mt < 2; mt++)
        #pragma unroll
        for (int nt = 0; nt < 8; nt++)
            #pragma unroll
            for (int i = 0; i < 4; i++) acc[mt][nt][i] = 0.f;

    const int nch = Kpad >> 5;
    const int npass = (A2h != nullptr) ? 2 : 1;
    const int T = npass * nch;

    auto issue = [&](int it, int st) {
        if (tid == 0) {
            int pass = (it >= nch) ? 1 : 0;
            int ch = it - pass * nch;
            const __nv_bfloat16* AH = pass ? A2h : A1h;
            const __nv_bfloat16* AL = pass ? A2l : A1l;
            const __nv_bfloat16* BH = pass ? B2h : B1h;
            const __nv_bfloat16* BL = pass ? B2l : B1l;
            uint32_t mb = mbase + st * 8;
            asm volatile("mbarrier.arrive.expect_tx.shared.b64 _, [%0], %1;"
                         :: "r"(mb), "r"(40960u) : "memory");
            uint32_t sb = ubase + st * STAGE_B;
            size_t at = ((size_t)blockIdx.y * nch + ch) * TILE_E;
            size_t bt = ((size_t)blockIdx.x * nch + ch) * TILE_E;
            bulkcp(sb,              AH + at, mb);
            bulkcp(sb + TILE_B,     AL + at, mb);
            bulkcp(sb + 2 * TILE_B, BH + bt, mb);
            bulkcp(sb + 3 * TILE_B, BL + bt, mb);
        }
    };

    int ph0 = 0, ph1 = 0;
    issue(0, 0);

    #pragma unroll 1
    for (int it = 0; it < T; ++it) {
        if (it + 1 < T) issue(it + 1, (it + 1) & 1);
        int st = it & 1;
        mbar_wait(mbase + st * 8, st ? ph1 : ph0);
        if (st) ph1 ^= 1; else ph0 ^= 1;

        uint32_t sb = ubase + st * STAGE_B;
        uint32_t uAh = sb, uAl = sb + TILE_B;
        uint32_t uBh = sb + 2 * TILE_B, uBl = sb + 3 * TILE_B;

        #pragma unroll
        for (int ks = 0; ks < 2; ++ks) {
            int kb = ks * 32;
            unsigned ah[2][4], al[2][4];
            #pragma unroll
            for (int mt = 0; mt < 2; mt++) {
                uint32_t ao = (uint32_t)((m0w + mt * 16 + a_row) * 80
                                         + kb + a_koff);
                ldm_x4(ah[mt], uAh + ao);
                ldm_x4(al[mt], uAl + ao);
            }
            #pragma unroll
            for (int nt = 0; nt < 8; nt++) {
                uint32_t bo = (uint32_t)((n0w + nt * 8 + b_row) * 80
                                         + kb + b_koff);
                unsigned bh[2], bl[2];
                ldm_x2(bh, uBh + bo);
                ldm_x2(bl, uBl + bo);
                #pragma unroll
                for (int mt = 0; mt < 2; mt++) {
                    mma_bf16(acc[mt][nt], ah[mt], bh[0], bh[1]);
                    mma_bf16(acc[mt][nt], al[mt], bh[0], bh[1]);
                    mma_bf16(acc[mt][nt], ah[mt], bl[0], bl[1]);
                }
            }
        }
        __syncthreads();   // all reads done before next bulk overwrites stage
    }

    // ---- Epilogue ----
    const int nchC = M >> 5;
    #pragma unroll
    for (int mt = 0; mt < 2; mt++) {
        #pragma unroll
        for (int nt = 0; nt < 8; nt++) {
            int r = rowBase + m0w + mt * 16 + gid;
            int c = colBase + n0w + nt * 8 + tig * 2;
            float b0v = bias[c], b1v = bias[c + 1];
            #pragma unroll
            for (int half = 0; half < 2; ++half) {
                int rr = r + half * 8;
                if (rr >= N) continue;
                float v0 = acc[mt][nt][2 * half + 0] + b0v;
                float v1 = acc[mt][nt][2 * half + 1] + b1v;
                if (do_relu) {
                    v0 = v0 > 0.f ? v0 : 0.f;
                    v1 = v1 > 0.f ? v1 : 0.f;
                }
                if (C) {
                    size_t o = (size_t)rr * M + c;
                    C[o] = v0;
                    C[o + 1] = v1;
                }
                if (Chi) {
                    size_t o = ((size_t)blockIdx.y * nchC + (c >> 5)) * TILE_E
                             + (rr & 127) * 40 + (c & 31);
                    __nv_bfloat162 hh = __floats2bfloat162_rn(v0, v1);
                    __nv_bfloat162 ll = __floats2bfloat162_rn(
                        v0 - __bfloat162float(hh.x), v1 - __bfloat162float(hh.y));
                    *(unsigned*)(Chi + o) = *(unsigned*)&hh;
                    *(unsigned*)(Clo + o) = *(unsigned*)&ll;
                }
            }
        }
    }
}

// ---------------------------------------------------------------------------
// LayerNorm(128) + ReLU + pooling.  Warp per row group; no block syncs.
// ---------------------------------------------------------------------------
#define LNW 32

__global__ __launch_bounds__(256)
void ln_pool(const float* __restrict__ z, const float* __restrict__ lng,
             const float* __restrict__ lnb, const int* __restrict__ batch,
             float* __restrict__ xa, float* __restrict__ pooled, int N) {
    int warp = (blockIdx.x * blockDim.x + threadIdx.x) >> 5;
    int lane = threadIdx.x & 31;
    int r0 = warp * LNW;
    if (r0 >= N) return;
    int r1 = min(r0 + LNW, N);

    float4 g = ((const float4*)lng)[lane];
    float4 b = ((const float4*)lnb)[lane];

    float4 pacc = make_float4(0.f, 0.f, 0.f, 0.f);
    int curg = -1;
    for (int r = r0; r < r1; ++r) {
        float4 v = ((const float4*)(z + (size_t)r * 128))[lane];
        float s = v.x + v.y + v.z + v.w;
        float s2 = v.x * v.x + v.y * v.y + v.z * v.z + v.w * v.w;
        #pragma unroll
        for (int o = 16; o > 0; o >>= 1) {
            s  += __shfl_xor_sync(0xffffffffu, s, o);
            s2 += __shfl_xor_sync(0xffffffffu, s2, o);
        }
        float mu = s * (1.f / 128.f);
        float var = s2 * (1.f / 128.f) - mu * mu;
        float inv = rsqrtf(var + 1e-5f);
        float4 zz;
        zz.x = fmaxf((v.x - mu) * inv * g.x + b.x, 0.f);
        zz.y = fmaxf((v.y - mu) * inv * g.y + b.y, 0.f);
        zz.z = fmaxf((v.z - mu) * inv * g.z + b.z, 0.f);
        zz.w = fmaxf((v.w - mu) * inv * g.w + b.w, 0.f);
        ((float4*)(xa + (size_t)r * 128))[lane] = zz;

        int gb = batch[r];
        if (gb != curg) {
            if (curg >= 0) {
                float* pd = pooled + (size_t)curg * 128 + lane * 4;
                atomicAdd(pd + 0, pacc.x);
                atomicAdd(pd + 1, pacc.y);
                atomicAdd(pd + 2, pacc.z);
                atomicAdd(pd + 3, pacc.w);
            }
            curg = gb;
            pacc = make_float4(0.f, 0.f, 0.f, 0.f);
        }
        pacc.x += zz.x; pacc.y += zz.y; pacc.z += zz.z; pacc.w += zz.w;
    }
    if (curg >= 0) {
        float* pd = pooled + (size_t)curg * 128 + lane * 4;
        atomicAdd(pd + 0, pacc.x);
        atomicAdd(pd + 1, pacc.y);
        atomicAdd(pd + 2, pacc.z);
        atomicAdd(pd + 3, pacc.w);
    }
}

// ---------------------------------------------------------------------------
// Launch (prep chain overlapped on a second stream via event fork/join)
// ---------------------------------------------------------------------------
extern "C" void kernel_launch(void* const* d_in, const int* in_sizes, int n_in,
                              void* d_out, int out_size) {
    const float* x     = (const float*)d_in[0];
    const int*   ei    = (const int*)d_in[1];
    const int*   batch = (const int*)d_in[2];
    const float* W1r = (const float*)d_in[3];
    const float* b1  = (const float*)d_in[4];
    const float* W1o = (const float*)d_in[5];
    const float* W2r = (const float*)d_in[6];
    const float* b2  = (const float*)d_in[7];
    const float* W2o = (const float*)d_in[8];
    const float* W3r = (const float*)d_in[9];
    const float* b3  = (const float*)d_in[10];
    const float* W3o = (const float*)d_in[11];
    const float* Wfc = (const float*)d_in[12];
    const float* bfc = (const float*)d_in[13];
    const float* lng = (const float*)d_in[14];
    const float* lnb = (const float*)d_in[15];

    float* out = (float*)d_out;
    float* x_atom = out;
    float* pooled = out + (size_t)N_NODES * 128;

    float *h1, *h2;
    __nv_bfloat16 *aggh, *aggl, *bAh, *bAl, *bBh, *bBl, *wth, *wtl;
    cudaGetSymbolAddress((void**)&h1, g_h1);
    cudaGetSymbolAddress((void**)&h2, g_h2);
    cudaGetSymbolAddress((void**)&aggh, g_agg_hi);
    cudaGetSymbolAddress((void**)&aggl, g_agg_lo);
    cudaGetSymbolAddress((void**)&bAh, g_bufA_hi);
    cudaGetSymbolAddress((void**)&bAl, g_bufA_lo);
    cudaGetSymbolAddress((void**)&bBh, g_bufB_hi);
    cudaGetSymbolAddress((void**)&bBl, g_bufB_lo);
    cudaGetSymbolAddress((void**)&wth, g_wt_hi);
    cudaGetSymbolAddress((void**)&wtl, g_wt_lo);

    cudaFuncSetAttribute(dual_gemm_bf16,
                         cudaFuncAttributeMaxDynamicSharedMemorySize, 81920);

    static cudaStream_t sB = nullptr;
    static cudaEvent_t evFork = nullptr, evJoin = nullptr;
    if (sB == nullptr) {
        cudaStreamCreateWithFlags(&sB, cudaStreamNonBlocking);
        cudaEventCreateWithFlags(&evFork, cudaEventDisableTiming);
        cudaEventCreateWithFlags(&evJoin, cudaEventDisableTiming);
    }

    const int gridY = NBLK;
    const int gatherBlocks = (N_NODES * 32 + 255) / 256;

    // ---- fork: weight/x prep on stream sB, CSR build on main stream ----
    cudaEventRecord(evFork, 0);
    cudaStreamWaitEvent(sB, evFork, 0);
    {
        PrepArgs pa;
        pa.W[0] = W1r; pa.K[0] = 78;  pa.M[0] = 256; pa.Kpad[0] = 96;  pa.off[0] = 0;
        pa.W[1] = W1o; pa.K[1] = 78;  pa.M[1] = 256; pa.Kpad[1] = 96;  pa.off[1] = 30720;
        pa.W[2] = W2r; pa.K[2] = 256; pa.M[2] = 512; pa.Kpad[2] = 256; pa.off[2] = 61440;
        pa.W[3] = W2o; pa.K[3] = 256; pa.M[3] = 512; pa.Kpad[3] = 256; pa.off[3] = 225280;
        pa.W[4] = W3r; pa.K[4] = 512; pa.M[4] = 512; pa.Kpad[4] = 512; pa.off[4] = 389120;
        pa.W[5] = W3o; pa.K[5] = 512; pa.M[5] = 512; pa.Kpad[5] = 512; pa.off[5] = 716800;
        pa.W[6] = Wfc; pa.K[6] = 512; pa.M[6] = 128; pa.Kpad[6] = 512; pa.off[6] = 1044480;
        dim3 grid((512 * 512 + 255) / 256, 7);
        prep_all<<<grid, 256, 0, sB>>>(pa, wth, wtl);
    }
    prep_x<<<(N_NODES * 96 + 255) / 256, 256, 0, sB>>>(x, bAh, bAl);
    cudaEventRecord(evJoin, sB);

    // main stream: CSR build + layer-1 gather
    {
        int* pcnt; cudaGetSymbolAddress((void**)&pcnt, g_cnt);
        zero_int<<<(N_NODES + 255) / 256, 256>>>(pcnt, N_NODES);
    }
    hist_kernel<<<(N_EDGES + 255) / 256, 256>>>(ei);
    scan1<<<(N_NODES + 1023) / 1024, 1024>>>();
    scan3<<<(N_NODES + 255) / 256, 256>>>();
    fill_kernel<<<(N_EDGES + 255) / 256, 256>>>(ei);
    gather78<<<gatherBlocks, 256>>>(x, aggh, aggl);

    // join before first GEMM (needs weights + prep_x output)
    cudaStreamWaitEvent(0, evJoin, 0);

    // ---- Layer 1: 78 -> 256 ----
    {
        dim3 grid(2, gridY);
        dual_gemm_bf16<<<grid, 256, 81920>>>(aggh, aggl, bAh, bAl,
                                             wth + 0, wtl + 0,
                                             wth + 30720, wtl + 30720,
                                             b1, h1, bBh, bBl,
                                             N_NODES, 96, 256, 1);
    }

    // ---- Layer 2: 256 -> 512 ----
    gather_vec4<<<gatherBlocks, 256>>>(h1, 256, aggh, aggl);
    {
        dim3 grid(4, gridY);
        dual_gemm_bf16<<<grid, 256, 81920>>>(aggh, aggl, bBh, bBl,
                                             wth + 61440, wtl + 61440,
                                             wth + 225280, wtl + 225280,
                                             b2, h2, bAh, bAl,
                                             N_NODES, 256, 512, 1);
    }

    // ---- Layer 3: 512 -> 512 ----
    gather_vec4<<<gatherBlocks, 256>>>(h2, 512, aggh, aggl);
    {
        dim3 grid(4, gridY);
        dual_gemm_bf16<<<grid, 256, 81920>>>(aggh, aggl, bAh, bAl,
                                             wth + 389120, wtl + 389120,
                                             wth + 716800, wtl + 716800,
                                             b3, (float*)nullptr, bBh, bBl,
                                             N_NODES, 512, 512, 1);
    }

    // ---- FC 512->128 via GEMM (no relu), then LN + ReLU + pool ----
    {
        dim3 grid(1, gridY);
        dual_gemm_bf16<<<grid, 256, 81920>>>(bBh, bBl,
                                             (__nv_bfloat16*)nullptr,
                                             (__nv_bfloat16*)nullptr,
                                             wth + 1044480, wtl + 1044480,
                                             (__nv_bfloat16*)nullptr,
                                             (__nv_bfloat16*)nullptr,
                                             bfc, h1,
                                             (__nv_bfloat16*)nullptr,
                                             (__nv_bfloat16*)nullptr,
                                             N_NODES, 512, 128, 0);
    }
    zero_kernel<<<128, 256>>>((float4*)pooled, N_GRAPHS * 128 / 4);
    {
        int warps = (N_NODES + LNW - 1) / LNW;
        ln_pool<<<(warps * 32 + 255) / 256, 256>>>(
            h1, lng, lnb, batch, x_atom, pooled, N_NODES);
    }
}

// round 13
// speedup vs baseline: 1.7756x; 1.0480x over previous
#include <cuda_runtime.h>
#include <cuda_bf16.h>
#include <cuda_fp16.h>
#include <cstdint>

#define N_NODES 50000
#define N_EDGES 800000
#define N_GRAPHS 1024
#define NBLK 391                 // ceil(50000/128)
#define TILE_E 5120              // elems per 10240B tile (128 rows x 40)
#define FEAT_E ((size_t)NBLK * 16 * TILE_E)

// ---------------- device-global scratch (allocation-free rule) -------------
__device__ float g_z[(size_t)N_NODES * 128];      // FC output
__device__ __half g_h16[(size_t)N_NODES * 512];   // fp16 inter-layer features
__device__ __half g_x16[(size_t)N_NODES * 78];    // fp16 copy of x
// tiled bf16 feature buffers: [block][chunk][128x40]
__device__ __nv_bfloat16 g_agg_hi[FEAT_E];
__device__ __nv_bfloat16 g_agg_lo[FEAT_E];
__device__ __nv_bfloat16 g_bufA_hi[FEAT_E];
__device__ __nv_bfloat16 g_bufA_lo[FEAT_E];
__device__ __nv_bfloat16 g_bufB_hi[FEAT_E];
__device__ __nv_bfloat16 g_bufB_lo[FEAT_E];
// tiled weights (bf16 hi/lo), offsets in elems:
// W1r:0 W1o:30720 W2r:61440 W2o:225280 W3r:389120 W3o:716800 Wfc:1044480
__device__ __nv_bfloat16 g_wt_hi[1126400];
__device__ __nv_bfloat16 g_wt_lo[1126400];
// CSR
__device__ int g_cnt[N_NODES];
__device__ int g_off[N_NODES + 1];
__device__ int g_cur[N_NODES];
__device__ int g_srcs[N_EDGES];
__device__ int g_bsum[64];

// ---------------------------------------------------------------------------
__global__ void zero_kernel(float4* __restrict__ p, int n4) {
    int i = blockIdx.x * blockDim.x + threadIdx.x;
    int stride = gridDim.x * blockDim.x;
    float4 z = make_float4(0.f, 0.f, 0.f, 0.f);
    for (; i < n4; i += stride) p[i] = z;
}

__global__ void zero_int(int* __restrict__ p, int n) {
    int i = blockIdx.x * blockDim.x + threadIdx.x;
    if (i < n) p[i] = 0;
}

// ---------------------------------------------------------------------------
// Fused weight prep -> tiled [colblock][chunk][128x40] bf16 hi/lo
// ---------------------------------------------------------------------------
struct PrepArgs {
    const float* W[7];
    int K[7];
    int M[7];
    int Kpad[7];
    int off[7];
};

__global__ void prep_all(PrepArgs a,
                         __nv_bfloat16* __restrict__ hi,
                         __nv_bfloat16* __restrict__ lo) {
    int seg = blockIdx.y;
    int idx = blockIdx.x * blockDim.x + threadIdx.x;
    int Kpad = a.Kpad[seg];
    if (idx >= a.M[seg] * Kpad) return;
    int n = idx / Kpad, k = idx % Kpad;
    int K = a.K[seg];
    int nch = Kpad >> 5;
    float v = (k < K) ? a.W[seg][(size_t)k * a.M[seg] + n] : 0.f;
    __nv_bfloat16 h = __float2bfloat16(v);
    size_t o = (size_t)a.off[seg]
             + ((size_t)(n >> 7) * nch + (k >> 5)) * TILE_E
             + (n & 127) * 40 + (k & 31);
    hi[o] = h;
    lo[o] = __float2bfloat16(v - __bfloat162float(h));
}

// x [N,78] fp32 -> tiled hi/lo (Kpad 96) + fp16 row-major copy
__global__ void prep_x(const float* __restrict__ x,
                       __nv_bfloat16* __restrict__ hi,
                       __nv_bfloat16* __restrict__ lo,
                       __half* __restrict__ x16) {
    int idx = blockIdx.x * blockDim.x + threadIdx.x;
    if (idx >= N_NODES * 96) return;
    int n = idx / 96, k = idx % 96;
    float v = (k < 78) ? x[(size_t)n * 78 + k] : 0.f;
    __nv_bfloat16 h = __float2bfloat16(v);
    size_t o = ((size_t)(n >> 7) * 3 + (k >> 5)) * TILE_E
             + (n & 127) * 40 + (k & 31);
    hi[o] = h;
    lo[o] = __float2bfloat16(v - __bfloat162float(h));
    if (k < 78) x16[(size_t)n * 78 + k] = __float2half(v);
}

// ---------------------------------------------------------------------------
// CSR build
// ---------------------------------------------------------------------------
__global__ void hist_kernel(const int* __restrict__ ei) {
    int e = blockIdx.x * blockDim.x + threadIdx.x;
    if (e < N_EDGES) atomicAdd(&g_cnt[ei[N_EDGES + e]], 1);
}

__global__ void scan1(void) {
    __shared__ int sm[1024];
    int tid = threadIdx.x;
    int i = blockIdx.x * 1024 + tid;
    int v = (i < N_NODES) ? g_cnt[i] : 0;
    sm[tid] = v;
    __syncthreads();
    for (int o = 1; o < 1024; o <<= 1) {
        int t = (tid >= o) ? sm[tid - o] : 0;
        __syncthreads();
        sm[tid] += t;
        __syncthreads();
    }
    if (i < N_NODES) g_off[i] = sm[tid] - v;
    if (tid == 1023) g_bsum[blockIdx.x] = sm[1023];
}

__global__ void scan3(void) {
    int i = blockIdx.x * blockDim.x + threadIdx.x;
    if (i < N_NODES) {
        int blk = i >> 10;
        int run = 0;
        for (int b = 0; b < blk; ++b) run += g_bsum[b];
        int o = g_off[i] + run;
        g_off[i] = o;
        g_cur[i] = o;
    }
    if (i == 0) g_off[N_NODES] = N_EDGES;
}

__global__ void fill_kernel(const int* __restrict__ ei) {
    int e = blockIdx.x * blockDim.x + threadIdx.x;
    if (e >= N_EDGES) return;
    int s = ei[e], t = ei[N_EDGES + e];
    int pos = atomicAdd(&g_cur[t], 1);
    g_srcs[pos] = s;
}

// ---------------------------------------------------------------------------
// CSR gather from fp16 x copy (layer 1) -> tiled bf16 hi/lo.  Warp per node.
// ---------------------------------------------------------------------------
__global__ void gather78(const __half* __restrict__ x,
                         __nv_bfloat16* __restrict__ ahi,
                         __nv_bfloat16* __restrict__ alo) {
    int n = (blockIdx.x * blockDim.x + threadIdx.x) >> 5;
    int lane = threadIdx.x & 31;
    if (n >= N_NODES) return;
    int jb = g_off[n], je = g_off[n + 1];
    float a0 = 0.f, a1 = 0.f, a2 = 0.f;
    for (int j = jb; j < je; ++j) {
        const __half* xr = x + (size_t)g_srcs[j] * 78;
        a0 += __half2float(__ldg(xr + lane));
        a1 += __half2float(__ldg(xr + lane + 32));
        if (lane < 14) a2 += __half2float(__ldg(xr + lane + 64));
    }
    float vals[3] = {a0, a1, (lane < 14) ? a2 : 0.f};
    size_t tbase = (size_t)(n >> 7) * 3;
    int rr = (n & 127) * 40 + lane;
    #pragma unroll
    for (int i = 0; i < 3; ++i) {
        size_t o = (tbase + i) * TILE_E + rr;
        __nv_bfloat16 h = __float2bfloat16(vals[i]);
        ahi[o] = h;
        alo[o] = __float2bfloat16(vals[i] - __bfloat162float(h));
    }
}

// CSR gather from fp16 features (layers 2,3): half the bytes of fp32.
// Each lane owns 8 consecutive cols per 256-col group (uint4 = 8 halves).
__global__ void gather_h16(const __half* __restrict__ x, int d,
                           __nv_bfloat16* __restrict__ ahi,
                           __nv_bfloat16* __restrict__ alo) {
    int n = (blockIdx.x * blockDim.x + threadIdx.x) >> 5;
    int lane = threadIdx.x & 31;
    if (n >= N_NODES) return;
    int jb = g_off[n], je = g_off[n + 1];
    int ng = d >> 8;                    // 256-elem groups (1 or 2)
    float acc[16];
    #pragma unroll
    for (int i = 0; i < 16; ++i) acc[i] = 0.f;
    for (int j = jb; j < je; ++j) {
        const __half* xr = x + (size_t)g_srcs[j] * d;
        #pragma unroll 2
        for (int g = 0; g < ng; ++g) {
            uint4 v = __ldg((const uint4*)(xr + g * 256) + lane);
            const __half2* hp = (const __half2*)&v;
            #pragma unroll
            for (int p = 0; p < 4; ++p) {
                float2 f = __half22float2(hp[p]);
                acc[g * 8 + p * 2]     += f.x;
                acc[g * 8 + p * 2 + 1] += f.y;
            }
        }
    }
    size_t tb = (size_t)(n >> 7) * (d >> 5);
    int rbase = (n & 127) * 40;
    for (int g = 0; g < ng; ++g) {
        int c0 = g * 256 + lane * 8;    // 8-aligned column base
        int ch = c0 >> 5;
        int co = c0 & 31;               // 0, 8, 16, 24
        #pragma unroll
        for (int hf = 0; hf < 2; ++hf) {
            float a0 = acc[g * 8 + hf * 4 + 0];
            float a1 = acc[g * 8 + hf * 4 + 1];
            float a2 = acc[g * 8 + hf * 4 + 2];
            float a3 = acc[g * 8 + hf * 4 + 3];
            __nv_bfloat162 h01 = __floats2bfloat162_rn(a0, a1);
            __nv_bfloat162 h23 = __floats2bfloat162_rn(a2, a3);
            __nv_bfloat162 l01 = __floats2bfloat162_rn(
                a0 - __bfloat162float(h01.x), a1 - __bfloat162float(h01.y));
            __nv_bfloat162 l23 = __floats2bfloat162_rn(
                a2 - __bfloat162float(h23.x), a3 - __bfloat162float(h23.y));
            size_t o = (tb + ch) * TILE_E + rbase + co + hf * 4;
            *(uint2*)(ahi + o) = make_uint2(*(unsigned*)&h01, *(unsigned*)&h23);
            *(uint2*)(alo + o) = make_uint2(*(unsigned*)&l01, *(unsigned*)&l23);
        }
    }
}

// ---------------------------------------------------------------------------
// mma / ldmatrix / bulk-copy helpers
// ---------------------------------------------------------------------------
__device__ __forceinline__ void mma_bf16(float* c, const unsigned* a,
                                         unsigned b0, unsigned b1) {
    asm volatile(
        "mma.sync.aligned.m16n8k16.row.col.f32.bf16.bf16.f32 "
        "{%0,%1,%2,%3}, {%4,%5,%6,%7}, {%8,%9}, {%0,%1,%2,%3};"
        : "+f"(c[0]), "+f"(c[1]), "+f"(c[2]), "+f"(c[3])
        : "r"(a[0]), "r"(a[1]), "r"(a[2]), "r"(a[3]), "r"(b0), "r"(b1));
}

__device__ __forceinline__ void ldm_x4(unsigned* r, uint32_t addr) {
    asm volatile(
        "ldmatrix.sync.aligned.m8n8.x4.shared.b16 {%0,%1,%2,%3}, [%4];"
        : "=r"(r[0]), "=r"(r[1]), "=r"(r[2]), "=r"(r[3]) : "r"(addr));
}

__device__ __forceinline__ void ldm_x2(unsigned* r, uint32_t addr) {
    asm volatile(
        "ldmatrix.sync.aligned.m8n8.x2.shared.b16 {%0,%1}, [%2];"
        : "=r"(r[0]), "=r"(r[1]) : "r"(addr));
}

__device__ __forceinline__ void bulkcp(uint32_t dst, const void* src,
                                       uint32_t mbar) {
    asm volatile(
        "cp.async.bulk.shared::cluster.global.mbarrier::complete_tx::bytes "
        "[%0], [%1], %2, [%3];"
        :: "r"(dst), "l"(src), "r"(10240u), "r"(mbar) : "memory");
}

__device__ __forceinline__ void mbar_wait(uint32_t addr, uint32_t phase) {
    asm volatile(
        "{\n\t.reg .pred p;\n\t"
        "WL%=:\n\t"
        "mbarrier.try_wait.parity.acquire.cta.shared::cta.b64 p, [%0], %1, 0x989680;\n\t"
        "@p bra WD%=;\n\t"
        "bra WL%=;\n\t"
        "WD%=:\n\t}"
        :: "r"(addr), "r"(phase) : "memory");
}

// ---------------------------------------------------------------------------
// Dual/single GEMM (bf16 hi/lo 3-term split), cp.async.bulk double-buffered.
// Outputs: optional fp32 C (row-major), fp16 C16 (row-major), bf16 hi/lo tiled.
// ---------------------------------------------------------------------------
#define TILE_B 10240
#define STAGE_B 40960

__global__ __launch_bounds__(256, 2)
void dual_gemm_bf16(const __nv_bfloat16* __restrict__ A1h,
                    const __nv_bfloat16* __restrict__ A1l,
                    const __nv_bfloat16* __restrict__ A2h,
                    const __nv_bfloat16* __restrict__ A2l,
                    const __nv_bfloat16* __restrict__ B1h,
                    const __nv_bfloat16* __restrict__ B1l,
                    const __nv_bfloat16* __restrict__ B2h,
                    const __nv_bfloat16* __restrict__ B2l,
                    const float* __restrict__ bias, float* __restrict__ C,
                    __half* __restrict__ C16,
                    __nv_bfloat16* __restrict__ Chi,
                    __nv_bfloat16* __restrict__ Clo,
                    int N, int Kpad, int M, int do_relu) {
    extern __shared__ __align__(16) char dynsmem[];
    __shared__ __align__(8) uint64_t s_mbar[2];
    uint32_t ubase = (uint32_t)__cvta_generic_to_shared(dynsmem);
    uint32_t mbase = (uint32_t)__cvta_generic_to_shared(s_mbar);

    int tid = threadIdx.x;
    int lane = tid & 31, wid = tid >> 5;
    int wr = wid & 3, wc = wid >> 2;
    int m0w = wr * 32, n0w = wc * 64;
    int gid = lane >> 2, tig = lane & 3;

    int rowBase = blockIdx.y * 128;
    int colBase = blockIdx.x * 128;

    int a_row = (lane & 7) + ((lane >> 3) & 1) * 8;
    int a_koff = (lane >> 4) * 16;
    int b_row = lane & 7;
    int b_koff = ((lane >> 3) & 1) * 16;

    if (tid == 0) {
        asm volatile("mbarrier.init.shared.b64 [%0], 1;" :: "r"(mbase) : "memory");
        asm volatile("mbarrier.init.shared.b64 [%0], 1;" :: "r"(mbase + 8) : "memory");
    }
    __syncthreads();

    float acc[2][8][4];
    #pragma unroll
    for (int mt = 0; mt < 2; mt++)
        #pragma unroll
        for (int nt = 0; nt < 8; nt++)
            #pragma unroll
            for (int i = 0; i < 4; i++) acc[mt][nt][i] = 0.f;

    const int nch = Kpad >> 5;
    const int npass = (A2h != nullptr) ? 2 : 1;
    const int T = npass * nch;

    auto issue = [&](int it, int st) {
        if (tid == 0) {
            int pass = (it >= nch) ? 1 : 0;
            int ch = it - pass * nch;
            const __nv_bfloat16* AH = pass ? A2h : A1h;
            const __nv_bfloat16* AL = pass ? A2l : A1l;
            const __nv_bfloat16* BH = pass ? B2h : B1h;
            const __nv_bfloat16* BL = pass ? B2l : B1l;
            uint32_t mb = mbase + st * 8;
            asm volatile("mbarrier.arrive.expect_tx.shared.b64 _, [%0], %1;"
                         :: "r"(mb), "r"(40960u) : "memory");
            uint32_t sb = ubase + st * STAGE_B;
            size_t at = ((size_t)blockIdx.y * nch + ch) * TILE_E;
            size_t bt = ((size_t)blockIdx.x * nch + ch) * TILE_E;
            bulkcp(sb,              AH + at, mb);
            bulkcp(sb + TILE_B,     AL + at, mb);
            bulkcp(sb + 2 * TILE_B, BH + bt, mb);
            bulkcp(sb + 3 * TILE_B, BL + bt, mb);
        }
    };

    int ph0 = 0, ph1 = 0;
    issue(0, 0);

    #pragma unroll 1
    for (int it = 0; it < T; ++it) {
        if (it + 1 < T) issue(it + 1, (it + 1) & 1);
        int st = it & 1;
        mbar_wait(mbase + st * 8, st ? ph1 : ph0);
        if (st) ph1 ^= 1; else ph0 ^= 1;

        uint32_t sb = ubase + st * STAGE_B;
        uint32_t uAh = sb, uAl = sb + TILE_B;
        uint32_t uBh = sb + 2 * TILE_B, uBl = sb + 3 * TILE_B;

        #pragma unroll
        for (int ks = 0; ks < 2; ++ks) {
            int kb = ks * 32;
            unsigned ah[2][4], al[2][4];
            #pragma unroll
            for (int mt = 0; mt < 2; mt++) {
                uint32_t ao = (uint32_t)((m0w + mt * 16 + a_row) * 80
                                         + kb + a_koff);
                ldm_x4(ah[mt], uAh + ao);
                ldm_x4(al[mt], uAl + ao);
            }
            #pragma unroll
            for (int nt = 0; nt < 8; nt++) {
                uint32_t bo = (uint32_t)((n0w + nt * 8 + b_row) * 80
                                         + kb + b_koff);
                unsigned bh[2], bl[2];
                ldm_x2(bh, uBh + bo);
                ldm_x2(bl, uBl + bo);
                #pragma unroll
                for (int mt = 0; mt < 2; mt++) {
                    mma_bf16(acc[mt][nt], ah[mt], bh[0], bh[1]);
                    mma_bf16(acc[mt][nt], al[mt], bh[0], bh[1]);
                    mma_bf16(acc[mt][nt], ah[mt], bl[0], bl[1]);
                }
            }
        }
        __syncthreads();   // all reads done before next bulk overwrites stage
    }

    // ---- Epilogue ----
    const int nchC = M >> 5;
    #pragma unroll
    for (int mt = 0; mt < 2; mt++) {
        #pragma unroll
        for (int nt = 0; nt < 8; nt++) {
            int r = rowBase + m0w + mt * 16 + gid;
            int c = colBase + n0w + nt * 8 + tig * 2;
            float b0v = bias[c], b1v = bias[c + 1];
            #pragma unroll
            for (int half = 0; half < 2; ++half) {
                int rr = r + half * 8;
                if (rr >= N) continue;
                float v0 = acc[mt][nt][2 * half + 0] + b0v;
                float v1 = acc[mt][nt][2 * half + 1] + b1v;
                if (do_relu) {
                    v0 = v0 > 0.f ? v0 : 0.f;
                    v1 = v1 > 0.f ? v1 : 0.f;
                }
                if (C) {
                    size_t o = (size_t)rr * M + c;
                    C[o] = v0;
                    C[o + 1] = v1;
                }
                if (C16) {
                    size_t o = (size_t)rr * M + c;
                    *(__half2*)(C16 + o) = __floats2half2_rn(v0, v1);
                }
                if (Chi) {
                    size_t o = ((size_t)blockIdx.y * nchC + (c >> 5)) * TILE_E
                             + (rr & 127) * 40 + (c & 31);
                    __nv_bfloat162 hh = __floats2bfloat162_rn(v0, v1);
                    __nv_bfloat162 ll = __floats2bfloat162_rn(
                        v0 - __bfloat162float(hh.x), v1 - __bfloat162float(hh.y));
                    *(unsigned*)(Chi + o) = *(unsigned*)&hh;
                    *(unsigned*)(Clo + o) = *(unsigned*)&ll;
                }
            }
        }
    }
}

// ---------------------------------------------------------------------------
// LayerNorm(128) + ReLU + pooling.  Warp per row group; no block syncs.
// ---------------------------------------------------------------------------
#define LNW 32

__global__ __launch_bounds__(256)
void ln_pool(const float* __restrict__ z, const float* __restrict__ lng,
             const float* __restrict__ lnb, const int* __restrict__ batch,
             float* __restrict__ xa, float* __restrict__ pooled, int N) {
    int warp = (blockIdx.x * blockDim.x + threadIdx.x) >> 5;
    int lane = threadIdx.x & 31;
    int r0 = warp * LNW;
    if (r0 >= N) return;
    int r1 = min(r0 + LNW, N);

    float4 g = ((const float4*)lng)[lane];
    float4 b = ((const float4*)lnb)[lane];

    float4 pacc = make_float4(0.f, 0.f, 0.f, 0.f);
    int curg = -1;
    for (int r = r0; r < r1; ++r) {
        float4 v = ((const float4*)(z + (size_t)r * 128))[lane];
        float s = v.x + v.y + v.z + v.w;
        float s2 = v.x * v.x + v.y * v.y + v.z * v.z + v.w * v.w;
        #pragma unroll
        for (int o = 16; o > 0; o >>= 1) {
            s  += __shfl_xor_sync(0xffffffffu, s, o);
            s2 += __shfl_xor_sync(0xffffffffu, s2, o);
        }
        float mu = s * (1.f / 128.f);
        float var = s2 * (1.f / 128.f) - mu * mu;
        float inv = rsqrtf(var + 1e-5f);
        float4 zz;
        zz.x = fmaxf((v.x - mu) * inv * g.x + b.x, 0.f);
        zz.y = fmaxf((v.y - mu) * inv * g.y + b.y, 0.f);
        zz.z = fmaxf((v.z - mu) * inv * g.z + b.z, 0.f);
        zz.w = fmaxf((v.w - mu) * inv * g.w + b.w, 0.f);
        ((float4*)(xa + (size_t)r * 128))[lane] = zz;

        int gb = batch[r];
        if (gb != curg) {
            if (curg >= 0) {
                float* pd = pooled + (size_t)curg * 128 + lane * 4;
                atomicAdd(pd + 0, pacc.x);
                atomicAdd(pd + 1, pacc.y);
                atomicAdd(pd + 2, pacc.z);
                atomicAdd(pd + 3, pacc.w);
            }
            curg = gb;
            pacc = make_float4(0.f, 0.f, 0.f, 0.f);
        }
        pacc.x += zz.x; pacc.y += zz.y; pacc.z += zz.z; pacc.w += zz.w;
    }
    if (curg >= 0) {
        float* pd = pooled + (size_t)curg * 128 + lane * 4;
        atomicAdd(pd + 0, pacc.x);
        atomicAdd(pd + 1, pacc.y);
        atomicAdd(pd + 2, pacc.z);
        atomicAdd(pd + 3, pacc.w);
    }
}

// ---------------------------------------------------------------------------
// Launch (prep chain + pooled zero overlapped on a second stream)
// ---------------------------------------------------------------------------
extern "C" void kernel_launch(void* const* d_in, const int* in_sizes, int n_in,
                              void* d_out, int out_size) {
    const float* x     = (const float*)d_in[0];
    const int*   ei    = (const int*)d_in[1];
    const int*   batch = (const int*)d_in[2];
    const float* W1r = (const float*)d_in[3];
    const float* b1  = (const float*)d_in[4];
    const float* W1o = (const float*)d_in[5];
    const float* W2r = (const float*)d_in[6];
    const float* b2  = (const float*)d_in[7];
    const float* W2o = (const float*)d_in[8];
    const float* W3r = (const float*)d_in[9];
    const float* b3  = (const float*)d_in[10];
    const float* W3o = (const float*)d_in[11];
    const float* Wfc = (const float*)d_in[12];
    const float* bfc = (const float*)d_in[13];
    const float* lng = (const float*)d_in[14];
    const float* lnb = (const float*)d_in[15];

    float* out = (float*)d_out;
    float* x_atom = out;
    float* pooled = out + (size_t)N_NODES * 128;

    float* zbuf;
    __half *h16, *x16;
    __nv_bfloat16 *aggh, *aggl, *bAh, *bAl, *bBh, *bBl, *wth, *wtl;
    cudaGetSymbolAddress((void**)&zbuf, g_z);
    cudaGetSymbolAddress((void**)&h16, g_h16);
    cudaGetSymbolAddress((void**)&x16, g_x16);
    cudaGetSymbolAddress((void**)&aggh, g_agg_hi);
    cudaGetSymbolAddress((void**)&aggl, g_agg_lo);
    cudaGetSymbolAddress((void**)&bAh, g_bufA_hi);
    cudaGetSymbolAddress((void**)&bAl, g_bufA_lo);
    cudaGetSymbolAddress((void**)&bBh, g_bufB_hi);
    cudaGetSymbolAddress((void**)&bBl, g_bufB_lo);
    cudaGetSymbolAddress((void**)&wth, g_wt_hi);
    cudaGetSymbolAddress((void**)&wtl, g_wt_lo);

    cudaFuncSetAttribute(dual_gemm_bf16,
                         cudaFuncAttributeMaxDynamicSharedMemorySize, 81920);

    static cudaStream_t sB = nullptr;
    static cudaEvent_t evFork = nullptr, evJoin = nullptr;
    if (sB == nullptr) {
        cudaStreamCreateWithFlags(&sB, cudaStreamNonBlocking);
        cudaEventCreateWithFlags(&evFork, cudaEventDisableTiming);
        cudaEventCreateWithFlags(&evJoin, cudaEventDisableTiming);
    }

    const int gridY = NBLK;
    const int gatherBlocks = (N_NODES * 32 + 255) / 256;

    // ---- fork: weight/x prep + pooled zero on stream sB ----
    cudaEventRecord(evFork, 0);
    cudaStreamWaitEvent(sB, evFork, 0);
    {
        PrepArgs pa;
        pa.W[0] = W1r; pa.K[0] = 78;  pa.M[0] = 256; pa.Kpad[0] = 96;  pa.off[0] = 0;
        pa.W[1] = W1o; pa.K[1] = 78;  pa.M[1] = 256; pa.Kpad[1] = 96;  pa.off[1] = 30720;
        pa.W[2] = W2r; pa.K[2] = 256; pa.M[2] = 512; pa.Kpad[2] = 256; pa.off[2] = 61440;
        pa.W[3] = W2o; pa.K[3] = 256; pa.M[3] = 512; pa.Kpad[3] = 256; pa.off[3] = 225280;
        pa.W[4] = W3r; pa.K[4] = 512; pa.M[4] = 512; pa.Kpad[4] = 512; pa.off[4] = 389120;
        pa.W[5] = W3o; pa.K[5] = 512; pa.M[5] = 512; pa.Kpad[5] = 512; pa.off[5] = 716800;
        pa.W[6] = Wfc; pa.K[6] = 512; pa.M[6] = 128; pa.Kpad[6] = 512; pa.off[6] = 1044480;
        dim3 grid((512 * 512 + 255) / 256, 7);
        prep_all<<<grid, 256, 0, sB>>>(pa, wth, wtl);
    }
    prep_x<<<(N_NODES * 96 + 255) / 256, 256, 0, sB>>>(x, bAh, bAl, x16);
    zero_kernel<<<128, 256, 0, sB>>>((float4*)pooled, N_GRAPHS * 128 / 4);
    cudaEventRecord(evJoin, sB);

    // main stream: CSR build
    {
        int* pcnt; cudaGetSymbolAddress((void**)&pcnt, g_cnt);
        zero_int<<<(N_NODES + 255) / 256, 256>>>(pcnt, N_NODES);
    }
    hist_kernel<<<(N_EDGES + 255) / 256, 256>>>(ei);
    scan1<<<(N_NODES + 1023) / 1024, 1024>>>();
    scan3<<<(N_NODES + 255) / 256, 256>>>();
    fill_kernel<<<(N_EDGES + 255) / 256, 256>>>(ei);

    // join before layer-1 gather (needs x16 from prep_x)
    cudaStreamWaitEvent(0, evJoin, 0);
    gather78<<<gatherBlocks, 256>>>(x16, aggh, aggl);

    // ---- Layer 1: 78 -> 256 (out: fp16 h + tiled bf16 hi/lo) ----
    {
        dim3 grid(2, gridY);
        dual_gemm_bf16<<<grid, 256, 81920>>>(aggh, aggl, bAh, bAl,
                                             wth + 0, wtl + 0,
                                             wth + 30720, wtl + 30720,
                                             b1, (float*)nullptr, h16, bBh, bBl,
                                             N_NODES, 96, 256, 1);
    }

    // ---- Layer 2: 256 -> 512 ----
    gather_h16<<<gatherBlocks, 256>>>(h16, 256, aggh, aggl);
    {
        dim3 grid(4, gridY);
        dual_gemm_bf16<<<grid, 256, 81920>>>(aggh, aggl, bBh, bBl,
                                             wth + 61440, wtl + 61440,
                                             wth + 225280, wtl + 225280,
                                             b2, (float*)nullptr, h16, bAh, bAl,
                                             N_NODES, 256, 512, 1);
    }

    // ---- Layer 3: 512 -> 512 ----
    gather_h16<<<gatherBlocks, 256>>>(h16, 512, aggh, aggl);
    {
        dim3 grid(4, gridY);
        dual_gemm_bf16<<<grid, 256, 81920>>>(aggh, aggl, bAh, bAl,
                                             wth + 389120, wtl + 389120,
                                             wth + 716800, wtl + 716800,
                                             b3, (float*)nullptr, (__half*)nullptr,
                                             bBh, bBl,
                                             N_NODES, 512, 512, 1);
    }

    // ---- FC 512->128 via GEMM (no relu), then LN + ReLU + pool ----
    {
        dim3 grid(1, gridY);
        dual_gemm_bf16<<<grid, 256, 81920>>>(bBh, bBl,
                                             (__nv_bfloat16*)nullptr,
                                             (__nv_bfloat16*)nullptr,
                                             wth + 1044480, wtl + 1044480,
                                             (__nv_bfloat16*)nullptr,
                                             (__nv_bfloat16*)nullptr,
                                             bfc, zbuf, (__half*)nullptr,
                                             (__nv_bfloat16*)nullptr,
                                             (__nv_bfloat16*)nullptr,
                                             N_NODES, 512, 128, 0);
    }
    {
        int warps = (N_NODES + LNW - 1) / LNW;
        ln_pool<<<(warps * 32 + 255) / 256, 256>>>(
            zbuf, lng, lnb, batch, x_atom, pooled, N_NODES);
    }
}